// round 2
// baseline (speedup 1.0000x reference)
#include <cuda_runtime.h>

// Problem constants
#define Bk      4
#define Ck      256
#define Pk      2304      // 48*48
#define INTERk  128
#define HEADSk  8
#define HDk     16

// Scratch (device globals — no runtime allocation allowed)
__device__ float g_Q[(size_t)Bk * INTERk * Pk];
__device__ float g_K[(size_t)Bk * INTERk * Pk];
__device__ float g_V[(size_t)Bk * INTERk * Pk];
__device__ float g_O[(size_t)Bk * INTERk * Pk];

// ---------------------------------------------------------------------------
// Kernel 1: fused 1x1-conv (channel GEMM) for Q/K/V.
// grid = (P/32, B, 3), block = 256 = 32 pixels x 8 channel-groups.
// Each thread: 16 output channels for 1 pixel. W rows broadcast within warp.
// ---------------------------------------------------------------------------
__global__ __launch_bounds__(256) void proj_qkv_kernel(
    const float* __restrict__ rgb, const float* __restrict__ depth, const float* __restrict__ rgbd,
    const float* __restrict__ Wq, const float* __restrict__ bq,
    const float* __restrict__ Wk, const float* __restrict__ bk,
    const float* __restrict__ Wv, const float* __restrict__ bv)
{
    const int z = blockIdx.z;
    const float* x    = (z == 0) ? rgb : (z == 1) ? depth : rgbd;
    const float* W    = (z == 0) ? Wq  : (z == 1) ? Wk    : Wv;
    const float* bias = (z == 0) ? bq  : (z == 1) ? bk    : bv;
    float* out        = (z == 0) ? g_Q : (z == 1) ? g_K   : g_V;

    const int b = blockIdx.y;
    const int p = blockIdx.x * 32 + (threadIdx.x & 31);
    const int g = threadIdx.x >> 5;        // 0..7 -> 16 out channels each

    float acc[16];
    #pragma unroll
    for (int i = 0; i < 16; i++) acc[i] = 0.f;

    const float* xb = x + (size_t)b * Ck * Pk + p;
    const float* Wg = W + (size_t)(g * 16) * Ck;

    for (int c = 0; c < Ck; c += 4) {
        const float x0 = xb[(c + 0) * Pk];
        const float x1 = xb[(c + 1) * Pk];
        const float x2 = xb[(c + 2) * Pk];
        const float x3 = xb[(c + 3) * Pk];
        #pragma unroll
        for (int i = 0; i < 16; i++) {
            const float4 w = *(const float4*)(Wg + i * Ck + c);
            acc[i] += w.x * x0 + w.y * x1 + w.z * x2 + w.w * x3;
        }
    }

    float* ob = out + ((size_t)b * INTERk + g * 16) * Pk + p;
    #pragma unroll
    for (int i = 0; i < 16; i++)
        ob[i * Pk] = acc[i] + bias[g * 16 + i];
}

// ---------------------------------------------------------------------------
// Kernel 2: attention, flash-style online softmax.
// grid = (P/128, HEADS, B), block = 128 (one thread per query).
// K/V tiles of 128 keys staged in smem as [key][d] float4; broadcast reads.
// ---------------------------------------------------------------------------
__global__ __launch_bounds__(128) void attn_kernel()
{
    __shared__ float Ks[128 * HDk];
    __shared__ float Vs[128 * HDk];

    const int tid = threadIdx.x;
    const int b = blockIdx.z;
    const int h = blockIdx.y;
    const int q = blockIdx.x * 128 + tid;

    const float* Qg = g_Q + ((size_t)b * INTERk + h * HDk) * Pk;
    const float* Kg = g_K + ((size_t)b * INTERk + h * HDk) * Pk;
    const float* Vg = g_V + ((size_t)b * INTERk + h * HDk) * Pk;

    float qr[HDk];
    #pragma unroll
    for (int d = 0; d < HDk; d++) qr[d] = Qg[d * Pk + q] * 0.25f;  // scale = 1/sqrt(16)

    float m = -1e30f, l = 0.f;
    float o[HDk];
    #pragma unroll
    for (int d = 0; d < HDk; d++) o[d] = 0.f;

    for (int kt = 0; kt < Pk; kt += 128) {
        // Stage K/V tile: thread tid owns key j=tid, all 16 dims.
        float tk[HDk], tv[HDk];
        #pragma unroll
        for (int d = 0; d < HDk; d++) {
            tk[d] = Kg[d * Pk + kt + tid];
            tv[d] = Vg[d * Pk + kt + tid];
        }
        __syncthreads();   // prior tile reads done
        #pragma unroll
        for (int d4 = 0; d4 < 4; d4++) {
            ((float4*)Ks)[tid * 4 + d4] = make_float4(tk[d4*4], tk[d4*4+1], tk[d4*4+2], tk[d4*4+3]);
            ((float4*)Vs)[tid * 4 + d4] = make_float4(tv[d4*4], tv[d4*4+1], tv[d4*4+2], tv[d4*4+3]);
        }
        __syncthreads();

        for (int j = 0; j < 128; j++) {
            const float4* kj = (const float4*)(Ks + j * HDk);
            const float4 k0 = kj[0], k1 = kj[1], k2 = kj[2], k3 = kj[3];
            float s = qr[0]*k0.x + qr[1]*k0.y + qr[2]*k0.z + qr[3]*k0.w
                    + qr[4]*k1.x + qr[5]*k1.y + qr[6]*k1.z + qr[7]*k1.w
                    + qr[8]*k2.x + qr[9]*k2.y + qr[10]*k2.z + qr[11]*k2.w
                    + qr[12]*k3.x + qr[13]*k3.y + qr[14]*k3.z + qr[15]*k3.w;

            float pexp;
            if (s > m) {
                const float corr = __expf(m - s);
                l *= corr;
                #pragma unroll
                for (int d = 0; d < HDk; d++) o[d] *= corr;
                m = s;
                pexp = 1.f;
            } else {
                pexp = __expf(s - m);
            }
            l += pexp;

            const float4* vj = (const float4*)(Vs + j * HDk);
            const float4 v0 = vj[0], v1 = vj[1], v2 = vj[2], v3 = vj[3];
            o[0]  += pexp * v0.x;  o[1]  += pexp * v0.y;  o[2]  += pexp * v0.z;  o[3]  += pexp * v0.w;
            o[4]  += pexp * v1.x;  o[5]  += pexp * v1.y;  o[6]  += pexp * v1.z;  o[7]  += pexp * v1.w;
            o[8]  += pexp * v2.x;  o[9]  += pexp * v2.y;  o[10] += pexp * v2.z;  o[11] += pexp * v2.w;
            o[12] += pexp * v3.x;  o[13] += pexp * v3.y;  o[14] += pexp * v3.z;  o[15] += pexp * v3.w;
        }
    }

    const float inv = 1.f / l;
    float* Og = g_O + ((size_t)b * INTERk + h * HDk) * Pk;
    #pragma unroll
    for (int d = 0; d < HDk; d++)
        Og[d * Pk + q] = o[d] * inv;
}

// ---------------------------------------------------------------------------
// Kernel 3: output 1x1 conv + residual into 3 outputs.
// grid = (P/32, 2, B), block = 256 = 32 pixels x 8 groups; thread = 16 co.
// ---------------------------------------------------------------------------
__global__ __launch_bounds__(256) void out_kernel(
    const float* __restrict__ rgb, const float* __restrict__ depth, const float* __restrict__ rgbd,
    const float* __restrict__ Wo, const float* __restrict__ bo,
    float* __restrict__ out)
{
    const int b = blockIdx.z;
    const int p = blockIdx.x * 32 + (threadIdx.x & 31);
    const int g = threadIdx.x >> 5;
    const int co0 = blockIdx.y * 128 + g * 16;

    float acc[16];
    #pragma unroll
    for (int i = 0; i < 16; i++) acc[i] = 0.f;

    const float* Ob = g_O + (size_t)b * INTERk * Pk + p;
    const float* Wg = Wo + (size_t)co0 * INTERk;

    for (int ci = 0; ci < INTERk; ci += 4) {
        const float x0 = Ob[(ci + 0) * Pk];
        const float x1 = Ob[(ci + 1) * Pk];
        const float x2 = Ob[(ci + 2) * Pk];
        const float x3 = Ob[(ci + 3) * Pk];
        #pragma unroll
        for (int i = 0; i < 16; i++) {
            const float4 w = *(const float4*)(Wg + i * INTERk + ci);
            acc[i] += w.x * x0 + w.y * x1 + w.z * x2 + w.w * x3;
        }
    }

    const size_t N1 = (size_t)Bk * Ck * Pk;
    #pragma unroll
    for (int i = 0; i < 16; i++) {
        const int co = co0 + i;
        const size_t idx = ((size_t)b * Ck + co) * Pk + p;
        const float r = acc[i] + bo[co];
        out[idx]          = rgb[idx]   + r;
        out[N1 + idx]     = depth[idx] + r;
        out[2 * N1 + idx] = rgbd[idx]  + r;
    }
}

// ---------------------------------------------------------------------------
extern "C" void kernel_launch(void* const* d_in, const int* in_sizes, int n_in,
                              void* d_out, int out_size)
{
    const float* rgb   = (const float*)d_in[0];
    const float* depth = (const float*)d_in[1];
    const float* rgbd  = (const float*)d_in[2];
    const float* Wq = (const float*)d_in[3];
    const float* bq = (const float*)d_in[4];
    const float* Wk = (const float*)d_in[5];
    const float* bk = (const float*)d_in[6];
    const float* Wv = (const float*)d_in[7];
    const float* bv = (const float*)d_in[8];
    const float* Wo = (const float*)d_in[9];
    const float* bo = (const float*)d_in[10];
    float* out = (float*)d_out;

    proj_qkv_kernel<<<dim3(Pk / 32, Bk, 3), 256>>>(rgb, depth, rgbd,
                                                   Wq, bq, Wk, bk, Wv, bv);
    attn_kernel<<<dim3(Pk / 128, HEADSk, Bk), 128>>>();
    out_kernel<<<dim3(Pk / 32, 2, Bk), 256>>>(rgb, depth, rgbd, Wo, bo, out);
}

// round 3
// speedup vs baseline: 1.6866x; 1.6866x over previous
#include <cuda_runtime.h>

#define Bk      4
#define Ck      256
#define Pk      2304      // 48*48
#define INTERk  128
#define HEADSk  8
#define HDk     16

typedef unsigned long long u64;

// ---- packed f32x2 helpers (Blackwell FFMA2 via PTX) -----------------------
__device__ __forceinline__ u64 pack2(float lo, float hi) {
    u64 r; asm("mov.b64 %0,{%1,%2};" : "=l"(r) : "f"(lo), "f"(hi)); return r;
}
__device__ __forceinline__ float2 unpk(u64 v) {
    float2 f; asm("mov.b64 {%0,%1},%2;" : "=f"(f.x), "=f"(f.y) : "l"(v)); return f;
}
__device__ __forceinline__ u64 fma2(u64 a, u64 b, u64 c) {
    u64 d; asm("fma.rn.f32x2 %0,%1,%2,%3;" : "=l"(d) : "l"(a), "l"(b), "l"(c)); return d;
}
__device__ __forceinline__ u64 mul2(u64 a, u64 b) {
    u64 d; asm("mul.rn.f32x2 %0,%1,%2;" : "=l"(d) : "l"(a), "l"(b)); return d;
}
__device__ __forceinline__ u64 add2(u64 a, u64 b) {
    u64 d; asm("add.rn.f32x2 %0,%1,%2;" : "=l"(d) : "l"(a), "l"(b)); return d;
}
__device__ __forceinline__ float ex2f(float x) {
    float r; asm("ex2.approx.ftz.f32 %0,%1;" : "=f"(r) : "f"(x)); return r;
}

// Scratch. Q/K/V transposed: [b][h][p][d] (d contiguous). O: [b][ci][p].
__device__ float g_Q[(size_t)Bk * INTERk * Pk];
__device__ float g_K[(size_t)Bk * INTERk * Pk];
__device__ float g_V[(size_t)Bk * INTERk * Pk];
__device__ float g_O[(size_t)Bk * INTERk * Pk];

// ---------------------------------------------------------------------------
// Kernel 1: QKV projection as smem-tiled GEMM.
// grid = (P/128, B, 3), block = 256. Tile: 128co x 128px, k-chunks of 32.
// Thread (tx=t&15, ty=t>>4): 8co x 8px micro-tile via f32x2.
// Epilogue writes transposed [b][h][px][d].
// ---------------------------------------------------------------------------
__global__ __launch_bounds__(256) void proj_kernel(
    const float* __restrict__ rgb, const float* __restrict__ depth, const float* __restrict__ rgbd,
    const float* __restrict__ Wq, const float* __restrict__ bq,
    const float* __restrict__ Wk, const float* __restrict__ bk,
    const float* __restrict__ Wv, const float* __restrict__ bv)
{
    __shared__ float Ws[32][128];   // [k][co]
    __shared__ float Xs[32][128];   // [k][px]

    const int z = blockIdx.z;
    const float* x    = (z == 0) ? rgb : (z == 1) ? depth : rgbd;
    const float* W    = (z == 0) ? Wq  : (z == 1) ? Wk    : Wv;
    const float* bias = (z == 0) ? bq  : (z == 1) ? bk    : bv;
    float* outT       = (z == 0) ? g_Q : (z == 1) ? g_K   : g_V;

    const int b   = blockIdx.y;
    const int px0 = blockIdx.x * 128;
    const int t   = threadIdx.x;
    const int tx  = t & 15;     // px group
    const int ty  = t >> 4;     // co group

    u64 acc[8][4];
    #pragma unroll
    for (int i = 0; i < 8; i++)
        #pragma unroll
        for (int j = 0; j < 4; j++) acc[i][j] = 0ull;

    const float* xb = x + (size_t)b * Ck * Pk + px0;

    for (int kc = 0; kc < Ck / 32; kc++) {
        const int ci0 = kc * 32;
        // stage W chunk transposed
        {
            const int co = t >> 1, hf = t & 1;
            const float* wr = W + (size_t)co * Ck + ci0 + hf * 16;
            float4 w0 = *(const float4*)(wr + 0);
            float4 w1 = *(const float4*)(wr + 4);
            float4 w2 = *(const float4*)(wr + 8);
            float4 w3 = *(const float4*)(wr + 12);
            const int kb = hf * 16;
            Ws[kb + 0][co] = w0.x;  Ws[kb + 1][co] = w0.y;  Ws[kb + 2][co] = w0.z;  Ws[kb + 3][co] = w0.w;
            Ws[kb + 4][co] = w1.x;  Ws[kb + 5][co] = w1.y;  Ws[kb + 6][co] = w1.z;  Ws[kb + 7][co] = w1.w;
            Ws[kb + 8][co] = w2.x;  Ws[kb + 9][co] = w2.y;  Ws[kb +10][co] = w2.z;  Ws[kb +11][co] = w2.w;
            Ws[kb +12][co] = w3.x;  Ws[kb +13][co] = w3.y;  Ws[kb +14][co] = w3.z;  Ws[kb +15][co] = w3.w;
        }
        // stage X chunk
        {
            const int k = t >> 3, seg = t & 7;
            const float* xr = xb + (size_t)(ci0 + k) * Pk + seg * 16;
            float4* xd = ((float4*)&Xs[k][0]) + seg * 4;
            xd[0] = *(const float4*)(xr + 0);
            xd[1] = *(const float4*)(xr + 4);
            xd[2] = *(const float4*)(xr + 8);
            xd[3] = *(const float4*)(xr + 12);
        }
        __syncthreads();

        #pragma unroll
        for (int k = 0; k < 32; k++) {
            const float4 aA = *(const float4*)&Ws[k][ty * 8];
            const float4 aB = *(const float4*)&Ws[k][ty * 8 + 4];
            const ulonglong2 bA = *(const ulonglong2*)&Xs[k][tx * 8];
            const ulonglong2 bB = *(const ulonglong2*)&Xs[k][tx * 8 + 4];
            float av[8] = {aA.x, aA.y, aA.z, aA.w, aB.x, aB.y, aB.z, aB.w};
            #pragma unroll
            for (int i = 0; i < 8; i++) {
                const u64 a2 = pack2(av[i], av[i]);
                acc[i][0] = fma2(a2, bA.x, acc[i][0]);
                acc[i][1] = fma2(a2, bA.y, acc[i][1]);
                acc[i][2] = fma2(a2, bB.x, acc[i][2]);
                acc[i][3] = fma2(a2, bB.y, acc[i][3]);
            }
        }
        __syncthreads();
    }

    // epilogue: add bias, write transposed [b*8+head][px][d]
    const int head = ty >> 1;
    const int dh0  = (ty & 1) * 8;
    float bi[8];
    #pragma unroll
    for (int i = 0; i < 8; i++) bi[i] = bias[ty * 8 + i];

    float* obase = outT + ((size_t)(b * HEADSk + head) * Pk) * HDk;
    #pragma unroll
    for (int jp = 0; jp < 4; jp++) {
        float2 f[8];
        #pragma unroll
        for (int i = 0; i < 8; i++) f[i] = unpk(acc[i][jp]);
        #pragma unroll
        for (int jj = 0; jj < 2; jj++) {
            const int px = px0 + tx * 8 + jp * 2 + jj;
            float v[8];
            #pragma unroll
            for (int i = 0; i < 8; i++) v[i] = (jj ? f[i].y : f[i].x) + bi[i];
            float4* dst = (float4*)(obase + (size_t)px * HDk + dh0);
            dst[0] = make_float4(v[0], v[1], v[2], v[3]);
            dst[1] = make_float4(v[4], v[5], v[6], v[7]);
        }
    }
}

// ---------------------------------------------------------------------------
// Kernel 2: attention. No-max softmax (scores bounded), ex2, f32x2 FMAs.
// grid = (P/256, HEADS, B), block = 128; each thread owns 2 queries.
// K/V tiles of 256 keys in smem as ulonglong2 [kv][d4][j].
// ---------------------------------------------------------------------------
#define TKEY 256
__global__ __launch_bounds__(128) void attn_kernel()
{
    __shared__ ulonglong2 KVs[2][4][TKEY];

    const int tid = threadIdx.x;
    const int b = blockIdx.z, h = blockIdx.y;
    const size_t bh = (size_t)(b * HEADSk + h) * Pk;
    const int q0 = blockIdx.x * 256 + tid;

    const float S = 0.25f * 1.44269504f;   // 1/sqrt(hd) * log2(e)

    u64 q2[2][8];
    #pragma unroll
    for (int qq = 0; qq < 2; qq++) {
        const float4* Qp = (const float4*)g_Q + (bh + q0 + qq * 128) * 4;
        #pragma unroll
        for (int c = 0; c < 4; c++) {
            const float4 v = Qp[c];
            q2[qq][c * 2 + 0] = pack2(v.x * S, v.y * S);
            q2[qq][c * 2 + 1] = pack2(v.z * S, v.w * S);
        }
    }

    u64 o2[2][8];
    #pragma unroll
    for (int qq = 0; qq < 2; qq++)
        #pragma unroll
        for (int c = 0; c < 8; c++) o2[qq][c] = 0ull;
    float l[2] = {0.f, 0.f};

    for (int kt = 0; kt < Pk; kt += TKEY) {
        const float4* Kp = (const float4*)g_K + (bh + kt) * 4;
        const float4* Vp = (const float4*)g_V + (bh + kt) * 4;
        float4 tk[2][4], tv[2][4];
        #pragma unroll
        for (int s = 0; s < 2; s++) {
            const int j = tid + s * 128;
            #pragma unroll
            for (int c = 0; c < 4; c++) {
                tk[s][c] = Kp[j * 4 + c];
                tv[s][c] = Vp[j * 4 + c];
            }
        }
        __syncthreads();
        #pragma unroll
        for (int s = 0; s < 2; s++) {
            const int j = tid + s * 128;
            #pragma unroll
            for (int c = 0; c < 4; c++) {
                KVs[0][c][j] = *(const ulonglong2*)&tk[s][c];
                KVs[1][c][j] = *(const ulonglong2*)&tv[s][c];
            }
        }
        __syncthreads();

        #pragma unroll 2
        for (int j = 0; j < TKEY; j++) {
            const ulonglong2 kA = KVs[0][0][j];
            const ulonglong2 kB = KVs[0][1][j];
            const ulonglong2 kC = KVs[0][2][j];
            const ulonglong2 kD = KVs[0][3][j];
            const ulonglong2 vA = KVs[1][0][j];
            const ulonglong2 vB = KVs[1][1][j];
            const ulonglong2 vC = KVs[1][2][j];
            const ulonglong2 vD = KVs[1][3][j];
            #pragma unroll
            for (int qq = 0; qq < 2; qq++) {
                u64 sa = mul2(q2[qq][0], kA.x);
                sa = fma2(q2[qq][1], kA.y, sa);
                sa = fma2(q2[qq][2], kB.x, sa);
                sa = fma2(q2[qq][3], kB.y, sa);
                u64 sb = mul2(q2[qq][4], kC.x);
                sb = fma2(q2[qq][5], kC.y, sb);
                sb = fma2(q2[qq][6], kD.x, sb);
                sb = fma2(q2[qq][7], kD.y, sb);
                const float2 sf = unpk(add2(sa, sb));
                const float p = ex2f(sf.x + sf.y);
                l[qq] += p;
                const u64 p2 = pack2(p, p);
                o2[qq][0] = fma2(p2, vA.x, o2[qq][0]);
                o2[qq][1] = fma2(p2, vA.y, o2[qq][1]);
                o2[qq][2] = fma2(p2, vB.x, o2[qq][2]);
                o2[qq][3] = fma2(p2, vB.y, o2[qq][3]);
                o2[qq][4] = fma2(p2, vC.x, o2[qq][4]);
                o2[qq][5] = fma2(p2, vC.y, o2[qq][5]);
                o2[qq][6] = fma2(p2, vD.x, o2[qq][6]);
                o2[qq][7] = fma2(p2, vD.y, o2[qq][7]);
            }
        }
    }

    // epilogue: normalize, write O as [b][ci][p]  (ci = h*16 + d)
    #pragma unroll
    for (int qq = 0; qq < 2; qq++) {
        const float inv = 1.f / l[qq];
        const int q = q0 + qq * 128;
        float* Og = g_O + ((size_t)b * INTERk + h * HDk) * Pk + q;
        #pragma unroll
        for (int c = 0; c < 8; c++) {
            const float2 f = unpk(o2[qq][c]);
            Og[(size_t)(2 * c + 0) * Pk] = f.x * inv;
            Og[(size_t)(2 * c + 1) * Pk] = f.y * inv;
        }
    }
}

// ---------------------------------------------------------------------------
// Kernel 3: output projection (GEMM 256co x 128ci) + bias + 3x residual.
// grid = (P/128, 2, B), block = 256. Same tiling as proj_kernel.
// ---------------------------------------------------------------------------
__global__ __launch_bounds__(256) void out_kernel(
    const float* __restrict__ rgb, const float* __restrict__ depth, const float* __restrict__ rgbd,
    const float* __restrict__ Wo, const float* __restrict__ bo,
    float* __restrict__ out)
{
    __shared__ float Ws[32][128];
    __shared__ float Xs[32][128];

    const int b    = blockIdx.z;
    const int cob  = blockIdx.y;       // 0..1 -> co block of 128
    const int px0  = blockIdx.x * 128;
    const int t    = threadIdx.x;
    const int tx   = t & 15;
    const int ty   = t >> 4;

    u64 acc[8][4];
    #pragma unroll
    for (int i = 0; i < 8; i++)
        #pragma unroll
        for (int j = 0; j < 4; j++) acc[i][j] = 0ull;

    const float* xb = g_O + (size_t)b * INTERk * Pk + px0;
    const float* W  = Wo + (size_t)(cob * 128) * INTERk;

    for (int kc = 0; kc < INTERk / 32; kc++) {
        const int ci0 = kc * 32;
        {
            const int co = t >> 1, hf = t & 1;
            const float* wr = W + (size_t)co * INTERk + ci0 + hf * 16;
            float4 w0 = *(const float4*)(wr + 0);
            float4 w1 = *(const float4*)(wr + 4);
            float4 w2 = *(const float4*)(wr + 8);
            float4 w3 = *(const float4*)(wr + 12);
            const int kb = hf * 16;
            Ws[kb + 0][co] = w0.x;  Ws[kb + 1][co] = w0.y;  Ws[kb + 2][co] = w0.z;  Ws[kb + 3][co] = w0.w;
            Ws[kb + 4][co] = w1.x;  Ws[kb + 5][co] = w1.y;  Ws[kb + 6][co] = w1.z;  Ws[kb + 7][co] = w1.w;
            Ws[kb + 8][co] = w2.x;  Ws[kb + 9][co] = w2.y;  Ws[kb +10][co] = w2.z;  Ws[kb +11][co] = w2.w;
            Ws[kb +12][co] = w3.x;  Ws[kb +13][co] = w3.y;  Ws[kb +14][co] = w3.z;  Ws[kb +15][co] = w3.w;
        }
        {
            const int k = t >> 3, seg = t & 7;
            const float* xr = xb + (size_t)(ci0 + k) * Pk + seg * 16;
            float4* xd = ((float4*)&Xs[k][0]) + seg * 4;
            xd[0] = *(const float4*)(xr + 0);
            xd[1] = *(const float4*)(xr + 4);
            xd[2] = *(const float4*)(xr + 8);
            xd[3] = *(const float4*)(xr + 12);
        }
        __syncthreads();

        #pragma unroll
        for (int k = 0; k < 32; k++) {
            const float4 aA = *(const float4*)&Ws[k][ty * 8];
            const float4 aB = *(const float4*)&Ws[k][ty * 8 + 4];
            const ulonglong2 bA = *(const ulonglong2*)&Xs[k][tx * 8];
            const ulonglong2 bB = *(const ulonglong2*)&Xs[k][tx * 8 + 4];
            float av[8] = {aA.x, aA.y, aA.z, aA.w, aB.x, aB.y, aB.z, aB.w};
            #pragma unroll
            for (int i = 0; i < 8; i++) {
                const u64 a2 = pack2(av[i], av[i]);
                acc[i][0] = fma2(a2, bA.x, acc[i][0]);
                acc[i][1] = fma2(a2, bA.y, acc[i][1]);
                acc[i][2] = fma2(a2, bB.x, acc[i][2]);
                acc[i][3] = fma2(a2, bB.y, acc[i][3]);
            }
        }
        __syncthreads();
    }

    const size_t N1 = (size_t)Bk * Ck * Pk;
    #pragma unroll
    for (int i = 0; i < 8; i++) {
        const int co = cob * 128 + ty * 8 + i;
        const float bb = bo[co];
        float r[8];
        #pragma unroll
        for (int jp = 0; jp < 4; jp++) {
            const float2 f = unpk(acc[i][jp]);
            r[jp * 2 + 0] = f.x + bb;
            r[jp * 2 + 1] = f.y + bb;
        }
        const size_t idx = ((size_t)b * Ck + co) * Pk + px0 + tx * 8;
        #pragma unroll
        for (int half = 0; half < 2; half++) {
            const float4 rr = make_float4(r[half*4+0], r[half*4+1], r[half*4+2], r[half*4+3]);
            const float4 a0 = *(const float4*)(rgb   + idx + half * 4);
            const float4 a1 = *(const float4*)(depth + idx + half * 4);
            const float4 a2 = *(const float4*)(rgbd  + idx + half * 4);
            *(float4*)(out + idx + half * 4)          = make_float4(a0.x + rr.x, a0.y + rr.y, a0.z + rr.z, a0.w + rr.w);
            *(float4*)(out + N1 + idx + half * 4)     = make_float4(a1.x + rr.x, a1.y + rr.y, a1.z + rr.z, a1.w + rr.w);
            *(float4*)(out + 2 * N1 + idx + half * 4) = make_float4(a2.x + rr.x, a2.y + rr.y, a2.z + rr.z, a2.w + rr.w);
        }
    }
}

// ---------------------------------------------------------------------------
extern "C" void kernel_launch(void* const* d_in, const int* in_sizes, int n_in,
                              void* d_out, int out_size)
{
    const float* rgb   = (const float*)d_in[0];
    const float* depth = (const float*)d_in[1];
    const float* rgbd  = (const float*)d_in[2];
    const float* Wq = (const float*)d_in[3];
    const float* bq = (const float*)d_in[4];
    const float* Wk = (const float*)d_in[5];
    const float* bk = (const float*)d_in[6];
    const float* Wv = (const float*)d_in[7];
    const float* bv = (const float*)d_in[8];
    const float* Wo = (const float*)d_in[9];
    const float* bo = (const float*)d_in[10];
    float* out = (float*)d_out;

    proj_kernel<<<dim3(Pk / 128, Bk, 3), 256>>>(rgb, depth, rgbd,
                                                Wq, bq, Wk, bk, Wv, bv);
    attn_kernel<<<dim3(Pk / TKEY, HEADSk, Bk), 128>>>();
    out_kernel<<<dim3(Pk / 128, 2, Bk), 256>>>(rgb, depth, rgbd, Wo, bo, out);
}

// round 4
// speedup vs baseline: 4.4417x; 2.6336x over previous
#include <cuda_runtime.h>
#include <cuda_bf16.h>

#define Bk      4
#define Ck      256
#define Pk      2304      // 48*48
#define INTERk  128
#define HEADSk  8
#define HDk     16

typedef unsigned long long u64;
typedef unsigned int u32;

// ---- packed f32x2 helpers -------------------------------------------------
__device__ __forceinline__ u64 pack2(float lo, float hi) {
    u64 r; asm("mov.b64 %0,{%1,%2};" : "=l"(r) : "f"(lo), "f"(hi)); return r;
}
__device__ __forceinline__ float2 unpk(u64 v) {
    float2 f; asm("mov.b64 {%0,%1},%2;" : "=f"(f.x), "=f"(f.y) : "l"(v)); return f;
}
__device__ __forceinline__ u64 fma2(u64 a, u64 b, u64 c) {
    u64 d; asm("fma.rn.f32x2 %0,%1,%2,%3;" : "=l"(d) : "l"(a), "l"(b), "l"(c)); return d;
}
__device__ __forceinline__ float ex2f(float x) {
    float r; asm("ex2.approx.ftz.f32 %0,%1;" : "=f"(r) : "f"(x)); return r;
}
// pack two f32 -> bf16x2 (lo, hi)
__device__ __forceinline__ u32 bf2(float lo, float hi) {
    u32 r; asm("cvt.rn.bf16x2.f32 %0,%1,%2;" : "=r"(r) : "f"(hi), "f"(lo)); return r;
}
// mma m16n8k16 bf16 -> f32 accum
__device__ __forceinline__ void mma16816(float c[4], const u32 a[4], const u32 b[2]) {
    asm("mma.sync.aligned.m16n8k16.row.col.f32.bf16.bf16.f32 "
        "{%0,%1,%2,%3},{%4,%5,%6,%7},{%8,%9},{%0,%1,%2,%3};"
        : "+f"(c[0]), "+f"(c[1]), "+f"(c[2]), "+f"(c[3])
        : "r"(a[0]), "r"(a[1]), "r"(a[2]), "r"(a[3]), "r"(b[0]), "r"(b[1]));
}

// Scratch (device globals)
__device__ __nv_bfloat16 gQ[(size_t)Bk * HEADSk * Pk * HDk];   // [b][h][p][d], pre-scaled
__device__ __nv_bfloat16 gK[(size_t)Bk * HEADSk * Pk * HDk];   // [b][h][p][d]
__device__ __nv_bfloat16 gVt[(size_t)Bk * HEADSk * HDk * Pk];  // [b][h][d][p]
__device__ float g_O[(size_t)Bk * INTERk * Pk];                // [b][ci][p]

// ---------------------------------------------------------------------------
// Kernel 1: QKV projection (scalar f32x2 GEMM), epilogue emits bf16 in
// MMA-friendly layouts. grid = (P/128, B, 3), block = 256.
// ---------------------------------------------------------------------------
__global__ __launch_bounds__(256, 2) void proj_kernel(
    const float* __restrict__ rgb, const float* __restrict__ depth, const float* __restrict__ rgbd,
    const float* __restrict__ Wq, const float* __restrict__ bq,
    const float* __restrict__ Wk, const float* __restrict__ bk,
    const float* __restrict__ Wv, const float* __restrict__ bv)
{
    __shared__ float Ws[32][128];   // [k][co]
    __shared__ float Xs[32][128];   // [k][px]

    const int z = blockIdx.z;
    const float* x    = (z == 0) ? rgb : (z == 1) ? depth : rgbd;
    const float* W    = (z == 0) ? Wq  : (z == 1) ? Wk    : Wv;
    const float* bias = (z == 0) ? bq  : (z == 1) ? bk    : bv;

    const int b   = blockIdx.y;
    const int px0 = blockIdx.x * 128;
    const int t   = threadIdx.x;
    const int tx  = t & 15;     // px group
    const int ty  = t >> 4;     // co group

    u64 acc[8][4];
    #pragma unroll
    for (int i = 0; i < 8; i++)
        #pragma unroll
        for (int j = 0; j < 4; j++) acc[i][j] = 0ull;

    const float* xb = x + (size_t)b * Ck * Pk + px0;

    for (int kc = 0; kc < Ck / 32; kc++) {
        const int ci0 = kc * 32;
        {
            const int co = t >> 1, hf = t & 1;
            const float* wr = W + (size_t)co * Ck + ci0 + hf * 16;
            float4 w0 = *(const float4*)(wr + 0);
            float4 w1 = *(const float4*)(wr + 4);
            float4 w2 = *(const float4*)(wr + 8);
            float4 w3 = *(const float4*)(wr + 12);
            const int kb = hf * 16;
            Ws[kb + 0][co] = w0.x;  Ws[kb + 1][co] = w0.y;  Ws[kb + 2][co] = w0.z;  Ws[kb + 3][co] = w0.w;
            Ws[kb + 4][co] = w1.x;  Ws[kb + 5][co] = w1.y;  Ws[kb + 6][co] = w1.z;  Ws[kb + 7][co] = w1.w;
            Ws[kb + 8][co] = w2.x;  Ws[kb + 9][co] = w2.y;  Ws[kb +10][co] = w2.z;  Ws[kb +11][co] = w2.w;
            Ws[kb +12][co] = w3.x;  Ws[kb +13][co] = w3.y;  Ws[kb +14][co] = w3.z;  Ws[kb +15][co] = w3.w;
        }
        {
            const int k = t >> 3, seg = t & 7;
            const float* xr = xb + (size_t)(ci0 + k) * Pk + seg * 16;
            float4* xd = ((float4*)&Xs[k][0]) + seg * 4;
            xd[0] = *(const float4*)(xr + 0);
            xd[1] = *(const float4*)(xr + 4);
            xd[2] = *(const float4*)(xr + 8);
            xd[3] = *(const float4*)(xr + 12);
        }
        __syncthreads();

        #pragma unroll
        for (int k = 0; k < 32; k++) {
            const float4 aA = *(const float4*)&Ws[k][ty * 8];
            const float4 aB = *(const float4*)&Ws[k][ty * 8 + 4];
            const ulonglong2 bA = *(const ulonglong2*)&Xs[k][tx * 8];
            const ulonglong2 bB = *(const ulonglong2*)&Xs[k][tx * 8 + 4];
            float av[8] = {aA.x, aA.y, aA.z, aA.w, aB.x, aB.y, aB.z, aB.w};
            #pragma unroll
            for (int i = 0; i < 8; i++) {
                const u64 a2 = pack2(av[i], av[i]);
                acc[i][0] = fma2(a2, bA.x, acc[i][0]);
                acc[i][1] = fma2(a2, bA.y, acc[i][1]);
                acc[i][2] = fma2(a2, bB.x, acc[i][2]);
                acc[i][3] = fma2(a2, bB.y, acc[i][3]);
            }
        }
        __syncthreads();
    }

    // epilogue: bias (+scale for Q), convert bf16, write MMA layouts
    const int head = ty >> 1;
    const int dh0  = (ty & 1) * 8;
    const size_t bh = (size_t)(b * HEADSk + head);
    float bi[8];
    #pragma unroll
    for (int i = 0; i < 8; i++) bi[i] = bias[ty * 8 + i];

    if (z < 2) {
        const float sc = (z == 0) ? 0.360673760f : 1.0f;   // 0.25 * log2(e)
        __nv_bfloat16* dstb = ((z == 0) ? gQ : gK) + bh * Pk * HDk + dh0;
        #pragma unroll
        for (int jp = 0; jp < 4; jp++) {
            float2 f[8];
            #pragma unroll
            for (int i = 0; i < 8; i++) f[i] = unpk(acc[i][jp]);
            #pragma unroll
            for (int jj = 0; jj < 2; jj++) {
                const int px = px0 + tx * 8 + jp * 2 + jj;
                float v[8];
                #pragma unroll
                for (int i = 0; i < 8; i++) v[i] = ((jj ? f[i].y : f[i].x) + bi[i]) * sc;
                uint4 pk;
                pk.x = bf2(v[0], v[1]);  pk.y = bf2(v[2], v[3]);
                pk.z = bf2(v[4], v[5]);  pk.w = bf2(v[6], v[7]);
                *(uint4*)(dstb + (size_t)px * HDk) = pk;
            }
        }
    } else {
        // V transposed: [bh][d][p]
        #pragma unroll
        for (int i = 0; i < 8; i++) {
            float v[8];
            #pragma unroll
            for (int jp = 0; jp < 4; jp++) {
                const float2 f = unpk(acc[i][jp]);
                v[jp * 2 + 0] = f.x + bi[i];
                v[jp * 2 + 1] = f.y + bi[i];
            }
            uint4 pk;
            pk.x = bf2(v[0], v[1]);  pk.y = bf2(v[2], v[3]);
            pk.z = bf2(v[4], v[5]);  pk.w = bf2(v[6], v[7]);
            *(uint4*)(gVt + (bh * HDk + dh0 + i) * Pk + px0 + tx * 8) = pk;
        }
    }
}

// ---------------------------------------------------------------------------
// Kernel 2: attention via bf16 HMMA (m16n8k16), no-max softmax with ex2.
// grid = (P/128, HEADS, B), block = 256 (8 warps); warp owns 16 q rows.
// ---------------------------------------------------------------------------
__global__ __launch_bounds__(256, 2) void attn_kernel()
{
    __shared__ __nv_bfloat16 Ks[128][24];    // [key][d], padded 16->24
    __shared__ __nv_bfloat16 Vs[16][136];    // [d][key], padded 128->136

    const int tid  = threadIdx.x;
    const int lane = tid & 31;
    const int w    = tid >> 5;
    const int b = blockIdx.z, h = blockIdx.y;
    const size_t bh = (size_t)(b * HEADSk + h);
    const int qw = blockIdx.x * 128 + w * 16;

    const __nv_bfloat16* Qb = gQ  + bh * Pk * HDk;
    const __nv_bfloat16* Kb = gK  + bh * Pk * HDk;
    const __nv_bfloat16* Vb = gVt + bh * HDk * Pk;

    // Q fragment (fixed for the whole kernel)
    u32 aQ[4];
    {
        const __nv_bfloat16* qp = Qb + (size_t)(qw + (lane >> 2)) * HDk + (lane & 3) * 2;
        aQ[0] = *(const u32*)(qp);
        aQ[1] = *(const u32*)(qp + 8 * HDk);
        aQ[2] = *(const u32*)(qp + 8);
        aQ[3] = *(const u32*)(qp + 8 * HDk + 8);
    }

    float O0[4] = {0.f, 0.f, 0.f, 0.f};
    float O1[4] = {0.f, 0.f, 0.f, 0.f};
    float l0 = 0.f, l1 = 0.f;

    for (int kt = 0; kt < Pk; kt += 128) {
        __syncthreads();
        if (tid < 128) {
            const uint4* src = (const uint4*)(Kb + (size_t)(kt + tid) * HDk);
            *(uint4*)&Ks[tid][0] = src[0];
            *(uint4*)&Ks[tid][8] = src[1];
        }
        {
            const int d = tid >> 4, seg = tid & 15;
            *(uint4*)&Vs[d][seg * 8] =
                *(const uint4*)(Vb + (size_t)d * Pk + kt + seg * 8);
        }
        __syncthreads();

        // S = Q * K^T for 16q x 128k
        float S[16][4];
        #pragma unroll
        for (int nt = 0; nt < 16; nt++) {
            S[nt][0] = 0.f; S[nt][1] = 0.f; S[nt][2] = 0.f; S[nt][3] = 0.f;
            u32 bK[2];
            bK[0] = *(const u32*)&Ks[nt * 8 + (lane >> 2)][(lane & 3) * 2];
            bK[1] = *(const u32*)&Ks[nt * 8 + (lane >> 2)][(lane & 3) * 2 + 8];
            mma16816(S[nt], aQ, bK);
        }

        // softmax weights (exp2, no running max: scores bounded) + row sums
        #pragma unroll
        for (int nt = 0; nt < 16; nt++) {
            S[nt][0] = ex2f(S[nt][0]);
            S[nt][1] = ex2f(S[nt][1]);
            S[nt][2] = ex2f(S[nt][2]);
            S[nt][3] = ex2f(S[nt][3]);
            l0 += S[nt][0] + S[nt][1];
            l1 += S[nt][2] + S[nt][3];
        }

        // O += P * V
        #pragma unroll
        for (int kk = 0; kk < 8; kk++) {
            u32 aP[4];
            aP[0] = bf2(S[2*kk][0],   S[2*kk][1]);
            aP[1] = bf2(S[2*kk][2],   S[2*kk][3]);
            aP[2] = bf2(S[2*kk+1][0], S[2*kk+1][1]);
            aP[3] = bf2(S[2*kk+1][2], S[2*kk+1][3]);
            u32 bV[2];
            bV[0] = *(const u32*)&Vs[(lane >> 2)][kk * 16 + (lane & 3) * 2];
            bV[1] = *(const u32*)&Vs[(lane >> 2)][kk * 16 + (lane & 3) * 2 + 8];
            mma16816(O0, aP, bV);
            bV[0] = *(const u32*)&Vs[8 + (lane >> 2)][kk * 16 + (lane & 3) * 2];
            bV[1] = *(const u32*)&Vs[8 + (lane >> 2)][kk * 16 + (lane & 3) * 2 + 8];
            mma16816(O1, aP, bV);
        }
    }

    // reduce row sums across the 4 lanes of each quad
    l0 += __shfl_xor_sync(0xffffffffu, l0, 1);
    l0 += __shfl_xor_sync(0xffffffffu, l0, 2);
    l1 += __shfl_xor_sync(0xffffffffu, l1, 1);
    l1 += __shfl_xor_sync(0xffffffffu, l1, 2);
    const float i0 = 1.f / l0;
    const float i1 = 1.f / l1;

    // write O as fp32 [b][h*16+d][p]
    float* Ob = g_O + ((size_t)b * INTERk + h * HDk) * Pk;
    const int q = qw + (lane >> 2);
    #pragma unroll
    for (int nd = 0; nd < 2; nd++) {
        const float* o = nd ? O1 : O0;
        const int d = nd * 8 + (lane & 3) * 2;
        Ob[(size_t)d       * Pk + q]     = o[0] * i0;
        Ob[(size_t)(d + 1) * Pk + q]     = o[1] * i0;
        Ob[(size_t)d       * Pk + q + 8] = o[2] * i1;
        Ob[(size_t)(d + 1) * Pk + q + 8] = o[3] * i1;
    }
}

// ---------------------------------------------------------------------------
// Kernel 3: output projection + bias + 3x residual. grid = (P/128, 2, B).
// ---------------------------------------------------------------------------
__global__ __launch_bounds__(256, 2) void out_kernel(
    const float* __restrict__ rgb, const float* __restrict__ depth, const float* __restrict__ rgbd,
    const float* __restrict__ Wo, const float* __restrict__ bo,
    float* __restrict__ out)
{
    __shared__ float Ws[32][128];
    __shared__ float Xs[32][128];

    const int b    = blockIdx.z;
    const int cob  = blockIdx.y;
    const int px0  = blockIdx.x * 128;
    const int t    = threadIdx.x;
    const int tx   = t & 15;
    const int ty   = t >> 4;

    u64 acc[8][4];
    #pragma unroll
    for (int i = 0; i < 8; i++)
        #pragma unroll
        for (int j = 0; j < 4; j++) acc[i][j] = 0ull;

    const float* xb = g_O + (size_t)b * INTERk * Pk + px0;
    const float* W  = Wo + (size_t)(cob * 128) * INTERk;

    for (int kc = 0; kc < INTERk / 32; kc++) {
        const int ci0 = kc * 32;
        {
            const int co = t >> 1, hf = t & 1;
            const float* wr = W + (size_t)co * INTERk + ci0 + hf * 16;
            float4 w0 = *(const float4*)(wr + 0);
            float4 w1 = *(const float4*)(wr + 4);
            float4 w2 = *(const float4*)(wr + 8);
            float4 w3 = *(const float4*)(wr + 12);
            const int kb = hf * 16;
            Ws[kb + 0][co] = w0.x;  Ws[kb + 1][co] = w0.y;  Ws[kb + 2][co] = w0.z;  Ws[kb + 3][co] = w0.w;
            Ws[kb + 4][co] = w1.x;  Ws[kb + 5][co] = w1.y;  Ws[kb + 6][co] = w1.z;  Ws[kb + 7][co] = w1.w;
            Ws[kb + 8][co] = w2.x;  Ws[kb + 9][co] = w2.y;  Ws[kb +10][co] = w2.z;  Ws[kb +11][co] = w2.w;
            Ws[kb +12][co] = w3.x;  Ws[kb +13][co] = w3.y;  Ws[kb +14][co] = w3.z;  Ws[kb +15][co] = w3.w;
        }
        {
            const int k = t >> 3, seg = t & 7;
            const float* xr = xb + (size_t)(ci0 + k) * Pk + seg * 16;
            float4* xd = ((float4*)&Xs[k][0]) + seg * 4;
            xd[0] = *(const float4*)(xr + 0);
            xd[1] = *(const float4*)(xr + 4);
            xd[2] = *(const float4*)(xr + 8);
            xd[3] = *(const float4*)(xr + 12);
        }
        __syncthreads();

        #pragma unroll
        for (int k = 0; k < 32; k++) {
            const float4 aA = *(const float4*)&Ws[k][ty * 8];
            const float4 aB = *(const float4*)&Ws[k][ty * 8 + 4];
            const ulonglong2 bA = *(const ulonglong2*)&Xs[k][tx * 8];
            const ulonglong2 bB = *(const ulonglong2*)&Xs[k][tx * 8 + 4];
            float av[8] = {aA.x, aA.y, aA.z, aA.w, aB.x, aB.y, aB.z, aB.w};
            #pragma unroll
            for (int i = 0; i < 8; i++) {
                const u64 a2 = pack2(av[i], av[i]);
                acc[i][0] = fma2(a2, bA.x, acc[i][0]);
                acc[i][1] = fma2(a2, bA.y, acc[i][1]);
                acc[i][2] = fma2(a2, bB.x, acc[i][2]);
                acc[i][3] = fma2(a2, bB.y, acc[i][3]);
            }
        }
        __syncthreads();
    }

    const size_t N1 = (size_t)Bk * Ck * Pk;
    #pragma unroll
    for (int i = 0; i < 8; i++) {
        const int co = cob * 128 + ty * 8 + i;
        const float bb = bo[co];
        float r[8];
        #pragma unroll
        for (int jp = 0; jp < 4; jp++) {
            const float2 f = unpk(acc[i][jp]);
            r[jp * 2 + 0] = f.x + bb;
            r[jp * 2 + 1] = f.y + bb;
        }
        const size_t idx = ((size_t)b * Ck + co) * Pk + px0 + tx * 8;
        #pragma unroll
        for (int half = 0; half < 2; half++) {
            const float4 rr = make_float4(r[half*4+0], r[half*4+1], r[half*4+2], r[half*4+3]);
            const float4 a0 = *(const float4*)(rgb   + idx + half * 4);
            const float4 a1 = *(const float4*)(depth + idx + half * 4);
            const float4 a2 = *(const float4*)(rgbd  + idx + half * 4);
            *(float4*)(out + idx + half * 4)          = make_float4(a0.x + rr.x, a0.y + rr.y, a0.z + rr.z, a0.w + rr.w);
            *(float4*)(out + N1 + idx + half * 4)     = make_float4(a1.x + rr.x, a1.y + rr.y, a1.z + rr.z, a1.w + rr.w);
            *(float4*)(out + 2 * N1 + idx + half * 4) = make_float4(a2.x + rr.x, a2.y + rr.y, a2.z + rr.z, a2.w + rr.w);
        }
    }
}

// ---------------------------------------------------------------------------
extern "C" void kernel_launch(void* const* d_in, const int* in_sizes, int n_in,
                              void* d_out, int out_size)
{
    const float* rgb   = (const float*)d_in[0];
    const float* depth = (const float*)d_in[1];
    const float* rgbd  = (const float*)d_in[2];
    const float* Wq = (const float*)d_in[3];
    const float* bq = (const float*)d_in[4];
    const float* Wk = (const float*)d_in[5];
    const float* bk = (const float*)d_in[6];
    const float* Wv = (const float*)d_in[7];
    const float* bv = (const float*)d_in[8];
    const float* Wo = (const float*)d_in[9];
    const float* bo = (const float*)d_in[10];
    float* out = (float*)d_out;

    proj_kernel<<<dim3(Pk / 128, Bk, 3), 256>>>(rgb, depth, rgbd,
                                                Wq, bq, Wk, bk, Wv, bv);
    attn_kernel<<<dim3(Pk / 128, HEADSk, Bk), 256>>>();
    out_kernel<<<dim3(Pk / 128, 2, Bk), 256>>>(rgb, depth, rgbd, Wo, bo, out);
}

// round 6
// speedup vs baseline: 4.7237x; 1.0635x over previous
#include <cuda_runtime.h>
#include <cuda_bf16.h>

#define Bk      4
#define Ck      256
#define Pk      2304      // 48*48
#define INTERk  128
#define HEADSk  8
#define HDk     16

typedef unsigned long long u64;
typedef unsigned int u32;

// ---- helpers --------------------------------------------------------------
__device__ __forceinline__ u32 bf2(float lo, float hi) {
    u32 r; asm("cvt.rn.bf16x2.f32 %0,%1,%2;" : "=r"(r) : "f"(hi), "f"(lo)); return r;
}
__device__ __forceinline__ float ex2f(float x) {
    float r; asm("ex2.approx.ftz.f32 %0,%1;" : "=f"(r) : "f"(x)); return r;
}
__device__ __forceinline__ void mma16816(float c[4], const u32 a[4], const u32 b[2]) {
    asm("mma.sync.aligned.m16n8k16.row.col.f32.bf16.bf16.f32 "
        "{%0,%1,%2,%3},{%4,%5,%6,%7},{%8,%9},{%0,%1,%2,%3};"
        : "+f"(c[0]), "+f"(c[1]), "+f"(c[2]), "+f"(c[3])
        : "r"(a[0]), "r"(a[1]), "r"(a[2]), "r"(a[3]), "r"(b[0]), "r"(b[1]));
}
// A fragment m16k16 from smem [row][stride], row-major, k contiguous
__device__ __forceinline__ void ldA(u32 a[4], const __nv_bfloat16* base, int stride,
                                    int mbase, int kbase, int lane) {
    const __nv_bfloat16* p = base + (size_t)(mbase + (lane >> 2)) * stride + kbase + (lane & 3) * 2;
    a[0] = *(const u32*)p;
    a[1] = *(const u32*)(p + 8 * stride);
    a[2] = *(const u32*)(p + 8);
    a[3] = *(const u32*)(p + 8 * stride + 8);
}
// B fragment n8k16 from smem [row=n][stride], k contiguous
__device__ __forceinline__ void ldB(u32 b[2], const __nv_bfloat16* base, int stride,
                                    int nbase, int kbase, int lane) {
    const __nv_bfloat16* p = base + (size_t)(nbase + (lane >> 2)) * stride + kbase + (lane & 3) * 2;
    b[0] = *(const u32*)p;
    b[1] = *(const u32*)(p + 8);
}

// Scratch (device globals)
__device__ __nv_bfloat16 gQ[(size_t)Bk * HEADSk * Pk * HDk];   // [b][h][p][d], pre-scaled
__device__ __nv_bfloat16 gK[(size_t)Bk * HEADSk * Pk * HDk];   // [b][h][p][d]
__device__ __nv_bfloat16 gVt[(size_t)Bk * HEADSk * HDk * Pk];  // [b][h][d][p]
__device__ __nv_bfloat16 gO[(size_t)Bk * Pk * INTERk];         // [b][p][ci]

// ---------------------------------------------------------------------------
// Kernel 1: QKV projection via bf16 HMMA.
// grid = (P/128, B, 3), block = 256 (8 warps: 4 m-warps x 2 n-warps).
// z<2 (Q,K): C[px][co]  (A = X^T tile, B = W) -> u32 stores to [px][d]
// z==2 (V):  C[co][px]  (A = W, B = X^T tile) -> u32 stores to [d][px]
// ---------------------------------------------------------------------------
#define XS_STRIDE 34   // 68B rows: <=2-way STS conflicts on transpose, conflict-free LDS.32
#define WS_STRIDE 40   // 80B rows: uint4 staging, conflict-free LDS.32

__global__ __launch_bounds__(256, 2) void proj_kernel(
    const float* __restrict__ rgb, const float* __restrict__ depth, const float* __restrict__ rgbd,
    const float* __restrict__ Wq, const float* __restrict__ bq,
    const float* __restrict__ Wk, const float* __restrict__ bk,
    const float* __restrict__ Wv, const float* __restrict__ bv)
{
    __shared__ __nv_bfloat16 Ws[128 * WS_STRIDE];   // [co][k]
    __shared__ __nv_bfloat16 Xs[128 * XS_STRIDE];   // [px][k] (transposed)

    const int z = blockIdx.z;
    const float* x    = (z == 0) ? rgb : (z == 1) ? depth : rgbd;
    const float* W    = (z == 0) ? Wq  : (z == 1) ? Wk    : Wv;
    const float* bias = (z == 0) ? bq  : (z == 1) ? bk    : bv;

    const int b    = blockIdx.y;
    const int px0  = blockIdx.x * 128;
    const int t    = threadIdx.x;
    const int lane = t & 31;
    const int w    = t >> 5;
    const int wm   = w >> 1;    // 0..3  (m blocks of 32)
    const int wn   = w & 1;     // 0..1  (n blocks of 64)

    float c[16][4];
    #pragma unroll
    for (int i = 0; i < 16; i++)
        #pragma unroll
        for (int j = 0; j < 4; j++) c[i][j] = 0.f;

    const float* xb = x + (size_t)b * Ck * Pk + px0;

    for (int kc = 0; kc < Ck / 32; kc++) {
        const int ci0 = kc * 32;
        // stage W chunk: [co][32] bf16
        {
            const int co = t >> 1, kh = (t & 1) * 16;
            const float* wr = W + (size_t)co * Ck + ci0 + kh;
            const float4 w0 = *(const float4*)(wr + 0);
            const float4 w1 = *(const float4*)(wr + 4);
            const float4 w2 = *(const float4*)(wr + 8);
            const float4 w3 = *(const float4*)(wr + 12);
            uint4 p0, p1;
            p0.x = bf2(w0.x, w0.y); p0.y = bf2(w0.z, w0.w);
            p0.z = bf2(w1.x, w1.y); p0.w = bf2(w1.z, w1.w);
            p1.x = bf2(w2.x, w2.y); p1.y = bf2(w2.z, w2.w);
            p1.z = bf2(w3.x, w3.y); p1.w = bf2(w3.z, w3.w);
            *(uint4*)&Ws[co * WS_STRIDE + kh]     = p0;
            *(uint4*)&Ws[co * WS_STRIDE + kh + 8] = p1;
        }
        // stage X chunk transposed: [px][32]
        {
            const int k = t >> 3, fq = t & 7;
            const float* xr = xb + (size_t)(ci0 + k) * Pk;
            #pragma unroll
            for (int j = 0; j < 4; j++) {
                const int px = (fq + j * 8) * 4;
                const float4 v = *(const float4*)(xr + px);
                Xs[(px + 0) * XS_STRIDE + k] = __float2bfloat16(v.x);
                Xs[(px + 1) * XS_STRIDE + k] = __float2bfloat16(v.y);
                Xs[(px + 2) * XS_STRIDE + k] = __float2bfloat16(v.z);
                Xs[(px + 3) * XS_STRIDE + k] = __float2bfloat16(v.w);
            }
        }
        __syncthreads();

        const __nv_bfloat16* Am = (z < 2) ? Xs : Ws;
        const __nv_bfloat16* Bm = (z < 2) ? Ws : Xs;
        const int As = (z < 2) ? XS_STRIDE : WS_STRIDE;
        const int Bs = (z < 2) ? WS_STRIDE : XS_STRIDE;

        #pragma unroll
        for (int k16 = 0; k16 < 2; k16++) {
            u32 a0[4], a1[4];
            ldA(a0, Am, As, wm * 32,      k16 * 16, lane);
            ldA(a1, Am, As, wm * 32 + 16, k16 * 16, lane);
            #pragma unroll
            for (int nt = 0; nt < 8; nt++) {
                u32 bb[2];
                ldB(bb, Bm, Bs, wn * 64 + nt * 8, k16 * 16, lane);
                mma16816(c[nt],     a0, bb);
                mma16816(c[8 + nt], a1, bb);
            }
        }
        __syncthreads();
    }

    // epilogue
    if (z < 2) {
        const float sc = (z == 0) ? 0.360673760f : 1.0f;   // Q: 0.25*log2(e)
        __nv_bfloat16* dst = (z == 0) ? gQ : gK;
        #pragma unroll
        for (int mt = 0; mt < 2; mt++)
            #pragma unroll
            for (int nt = 0; nt < 8; nt++) {
                const float* cc = c[mt * 8 + nt];
                const int px = px0 + wm * 32 + mt * 16 + (lane >> 2);
                const int co = wn * 64 + nt * 8 + (lane & 3) * 2;
                const int head = co >> 4, d = co & 15;
                const size_t base = (size_t)(b * HEADSk + head) * Pk;
                const float b0 = bias[co], b1 = bias[co + 1];
                *(u32*)&dst[(base + px) * HDk + d]       = bf2((cc[0] + b0) * sc, (cc[1] + b1) * sc);
                *(u32*)&dst[(base + px + 8) * HDk + d]   = bf2((cc[2] + b0) * sc, (cc[3] + b1) * sc);
            }
    } else {
        #pragma unroll
        for (int mt = 0; mt < 2; mt++)
            #pragma unroll
            for (int nt = 0; nt < 8; nt++) {
                const float* cc = c[mt * 8 + nt];
                const int px = px0 + wn * 64 + nt * 8 + (lane & 3) * 2;
                #pragma unroll
                for (int half = 0; half < 2; half++) {
                    const int co = wm * 32 + mt * 16 + (lane >> 2) + half * 8;
                    const int head = co >> 4, d = co & 15;
                    const float bb = bias[co];
                    *(u32*)&gVt[((size_t)(b * HEADSk + head) * HDk + d) * Pk + px] =
                        bf2(cc[half * 2] + bb, cc[half * 2 + 1] + bb);
                }
            }
    }
}

// ---------------------------------------------------------------------------
// Kernel 2: attention via bf16 HMMA, no-max softmax with ex2.
// grid = (P/128, HEADS, B), block = 256 (8 warps); warp owns 16 q rows.
// Epilogue writes O as bf16 [b][px][ci].
// ---------------------------------------------------------------------------
__global__ __launch_bounds__(256, 2) void attn_kernel()
{
    __shared__ __nv_bfloat16 Ks[128][24];    // [key][d], padded 16->24
    __shared__ __nv_bfloat16 Vs[16][136];    // [d][key], padded 128->136

    const int tid  = threadIdx.x;
    const int lane = tid & 31;
    const int w    = tid >> 5;
    const int b = blockIdx.z, h = blockIdx.y;
    const size_t bh = (size_t)(b * HEADSk + h);
    const int qw = blockIdx.x * 128 + w * 16;

    const __nv_bfloat16* Qb = gQ  + bh * Pk * HDk;
    const __nv_bfloat16* Kb = gK  + bh * Pk * HDk;
    const __nv_bfloat16* Vb = gVt + bh * HDk * Pk;

    u32 aQ[4];
    {
        const __nv_bfloat16* qp = Qb + (size_t)(qw + (lane >> 2)) * HDk + (lane & 3) * 2;
        aQ[0] = *(const u32*)(qp);
        aQ[1] = *(const u32*)(qp + 8 * HDk);
        aQ[2] = *(const u32*)(qp + 8);
        aQ[3] = *(const u32*)(qp + 8 * HDk + 8);
    }

    float O0[4] = {0.f, 0.f, 0.f, 0.f};
    float O1[4] = {0.f, 0.f, 0.f, 0.f};
    float l0 = 0.f, l1 = 0.f;

    for (int kt = 0; kt < Pk; kt += 128) {
        __syncthreads();
        if (tid < 128) {
            const uint4* src = (const uint4*)(Kb + (size_t)(kt + tid) * HDk);
            *(uint4*)&Ks[tid][0] = src[0];
            *(uint4*)&Ks[tid][8] = src[1];
        }
        {
            const int d = tid >> 4, seg = tid & 15;
            *(uint4*)&Vs[d][seg * 8] =
                *(const uint4*)(Vb + (size_t)d * Pk + kt + seg * 8);
        }
        __syncthreads();

        float S[16][4];
        #pragma unroll
        for (int nt = 0; nt < 16; nt++) {
            S[nt][0] = 0.f; S[nt][1] = 0.f; S[nt][2] = 0.f; S[nt][3] = 0.f;
            u32 bK[2];
            bK[0] = *(const u32*)&Ks[nt * 8 + (lane >> 2)][(lane & 3) * 2];
            bK[1] = *(const u32*)&Ks[nt * 8 + (lane >> 2)][(lane & 3) * 2 + 8];
            mma16816(S[nt], aQ, bK);
        }

        #pragma unroll
        for (int nt = 0; nt < 16; nt++) {
            S[nt][0] = ex2f(S[nt][0]);
            S[nt][1] = ex2f(S[nt][1]);
            S[nt][2] = ex2f(S[nt][2]);
            S[nt][3] = ex2f(S[nt][3]);
            l0 += S[nt][0] + S[nt][1];
            l1 += S[nt][2] + S[nt][3];
        }

        #pragma unroll
        for (int kk = 0; kk < 8; kk++) {
            u32 aP[4];
            aP[0] = bf2(S[2*kk][0],   S[2*kk][1]);
            aP[1] = bf2(S[2*kk][2],   S[2*kk][3]);
            aP[2] = bf2(S[2*kk+1][0], S[2*kk+1][1]);
            aP[3] = bf2(S[2*kk+1][2], S[2*kk+1][3]);
            u32 bV[2];
            bV[0] = *(const u32*)&Vs[(lane >> 2)][kk * 16 + (lane & 3) * 2];
            bV[1] = *(const u32*)&Vs[(lane >> 2)][kk * 16 + (lane & 3) * 2 + 8];
            mma16816(O0, aP, bV);
            bV[0] = *(const u32*)&Vs[8 + (lane >> 2)][kk * 16 + (lane & 3) * 2];
            bV[1] = *(const u32*)&Vs[8 + (lane >> 2)][kk * 16 + (lane & 3) * 2 + 8];
            mma16816(O1, aP, bV);
        }
    }

    l0 += __shfl_xor_sync(0xffffffffu, l0, 1);
    l0 += __shfl_xor_sync(0xffffffffu, l0, 2);
    l1 += __shfl_xor_sync(0xffffffffu, l1, 1);
    l1 += __shfl_xor_sync(0xffffffffu, l1, 2);
    const float i0 = 1.f / l0;
    const float i1 = 1.f / l1;

    // write O bf16 [b][px][ci]
    const int q = qw + (lane >> 2);
    __nv_bfloat16* Ob = gO + ((size_t)b * Pk) * INTERk + h * HDk;
    #pragma unroll
    for (int nd = 0; nd < 2; nd++) {
        const float* o = nd ? O1 : O0;
        const int d = nd * 8 + (lane & 3) * 2;
        *(u32*)&Ob[(size_t)q * INTERk + d]       = bf2(o[0] * i0, o[1] * i0);
        *(u32*)&Ob[(size_t)(q + 8) * INTERk + d] = bf2(o[2] * i1, o[3] * i1);
    }
}

// ---------------------------------------------------------------------------
// Kernel 3: output projection via bf16 HMMA + bias + 3x residual.
// grid = (P/128, 2, B), block = 256. C[co][px]; A = Wo (natural), B = O (natural).
// ---------------------------------------------------------------------------
__global__ __launch_bounds__(256, 2) void out_kernel(
    const float* __restrict__ rgb, const float* __restrict__ depth, const float* __restrict__ rgbd,
    const float* __restrict__ Wo, const float* __restrict__ bo,
    float* __restrict__ out)
{
    __shared__ __nv_bfloat16 Wos[128 * WS_STRIDE];  // [co][ci chunk]
    __shared__ __nv_bfloat16 Os[128 * WS_STRIDE];   // [px][ci chunk]

    const int b    = blockIdx.z;
    const int cob  = blockIdx.y;
    const int px0  = blockIdx.x * 128;
    const int t    = threadIdx.x;
    const int lane = t & 31;
    const int w    = t >> 5;
    const int wm   = w >> 1;    // co blocks of 32
    const int wn   = w & 1;     // px blocks of 64

    float c[16][4];
    #pragma unroll
    for (int i = 0; i < 16; i++)
        #pragma unroll
        for (int j = 0; j < 4; j++) c[i][j] = 0.f;

    for (int kc = 0; kc < INTERk / 32; kc++) {
        const int ci0 = kc * 32;
        // stage Wo chunk
        {
            const int co = t >> 1, kh = (t & 1) * 16;
            const float* wr = Wo + (size_t)(cob * 128 + co) * INTERk + ci0 + kh;
            const float4 w0 = *(const float4*)(wr + 0);
            const float4 w1 = *(const float4*)(wr + 4);
            const float4 w2 = *(const float4*)(wr + 8);
            const float4 w3 = *(const float4*)(wr + 12);
            uint4 p0, p1;
            p0.x = bf2(w0.x, w0.y); p0.y = bf2(w0.z, w0.w);
            p0.z = bf2(w1.x, w1.y); p0.w = bf2(w1.z, w1.w);
            p1.x = bf2(w2.x, w2.y); p1.y = bf2(w2.z, w2.w);
            p1.z = bf2(w3.x, w3.y); p1.w = bf2(w3.z, w3.w);
            *(uint4*)&Wos[co * WS_STRIDE + kh]     = p0;
            *(uint4*)&Wos[co * WS_STRIDE + kh + 8] = p1;
        }
        // stage O chunk (already [px][ci], bf16)
        {
            const int px = t >> 1, kh = (t & 1) * 16;
            const __nv_bfloat16* src = gO + ((size_t)b * Pk + px0 + px) * INTERk + ci0 + kh;
            *(uint4*)&Os[px * WS_STRIDE + kh]     = *(const uint4*)(src);
            *(uint4*)&Os[px * WS_STRIDE + kh + 8] = *(const uint4*)(src + 8);
        }
        __syncthreads();

        #pragma unroll
        for (int k16 = 0; k16 < 2; k16++) {
            u32 a0[4], a1[4];
            ldA(a0, Wos, WS_STRIDE, wm * 32,      k16 * 16, lane);
            ldA(a1, Wos, WS_STRIDE, wm * 32 + 16, k16 * 16, lane);
            #pragma unroll
            for (int nt = 0; nt < 8; nt++) {
                u32 bb[2];
                ldB(bb, Os, WS_STRIDE, wn * 64 + nt * 8, k16 * 16, lane);
                mma16816(c[nt],     a0, bb);
                mma16816(c[8 + nt], a1, bb);
            }
        }
        __syncthreads();
    }

    const size_t N1 = (size_t)Bk * Ck * Pk;
    #pragma unroll
    for (int mt = 0; mt < 2; mt++)
        #pragma unroll
        for (int nt = 0; nt < 8; nt++) {
            const float* cc = c[mt * 8 + nt];
            const int px = px0 + wn * 64 + nt * 8 + (lane & 3) * 2;
            #pragma unroll
            for (int half = 0; half < 2; half++) {
                const int co = cob * 128 + wm * 32 + mt * 16 + (lane >> 2) + half * 8;
                const float bb = bo[co];
                const float r0 = cc[half * 2]     + bb;
                const float r1 = cc[half * 2 + 1] + bb;
                const size_t idx = ((size_t)b * Ck + co) * Pk + px;
                const float2 a0 = *(const float2*)(rgb   + idx);
                const float2 a1 = *(const float2*)(depth + idx);
                const float2 a2 = *(const float2*)(rgbd  + idx);
                *(float2*)(out + idx)          = make_float2(a0.x + r0, a0.y + r1);
                *(float2*)(out + N1 + idx)     = make_float2(a1.x + r0, a1.y + r1);
                *(float2*)(out + 2 * N1 + idx) = make_float2(a2.x + r0, a2.y + r1);
            }
        }
}

// ---------------------------------------------------------------------------
extern "C" void kernel_launch(void* const* d_in, const int* in_sizes, int n_in,
                              void* d_out, int out_size)
{
    const float* rgb   = (const float*)d_in[0];
    const float* depth = (const float*)d_in[1];
    const float* rgbd  = (const float*)d_in[2];
    const float* Wq = (const float*)d_in[3];
    const float* bq = (const float*)d_in[4];
    const float* Wk = (const float*)d_in[5];
    const float* bk = (const float*)d_in[6];
    const float* Wv = (const float*)d_in[7];
    const float* bv = (const float*)d_in[8];
    const float* Wo = (const float*)d_in[9];
    const float* bo = (const float*)d_in[10];
    float* out = (float*)d_out;

    proj_kernel<<<dim3(Pk / 128, Bk, 3), 256>>>(rgb, depth, rgbd,
                                                Wq, bq, Wk, bk, Wv, bv);
    attn_kernel<<<dim3(Pk / 128, HEADSk, Bk), 256>>>();
    out_kernel<<<dim3(Pk / 128, 2, Bk), 256>>>(rgb, depth, rgbd, Wo, bo, out);
}

// round 8
// speedup vs baseline: 7.8695x; 1.6660x over previous
#include <cuda_runtime.h>
#include <cuda_bf16.h>

#define Bk      4
#define Ck      256
#define Pk      2304      // 48*48
#define INTERk  128
#define HEADSk  8
#define HDk     16

typedef unsigned long long u64;
typedef unsigned int u32;

// ---- helpers --------------------------------------------------------------
__device__ __forceinline__ u32 bf2(float lo, float hi) {
    u32 r; asm("cvt.rn.bf16x2.f32 %0,%1,%2;" : "=r"(r) : "f"(hi), "f"(lo)); return r;
}
__device__ __forceinline__ float ex2f(float x) {
    float r; asm("ex2.approx.ftz.f32 %0,%1;" : "=f"(r) : "f"(x)); return r;
}
__device__ __forceinline__ void mma16816(float c[4], const u32 a[4], const u32 b[2]) {
    asm("mma.sync.aligned.m16n8k16.row.col.f32.bf16.bf16.f32 "
        "{%0,%1,%2,%3},{%4,%5,%6,%7},{%8,%9},{%0,%1,%2,%3};"
        : "+f"(c[0]), "+f"(c[1]), "+f"(c[2]), "+f"(c[3])
        : "r"(a[0]), "r"(a[1]), "r"(a[2]), "r"(a[3]), "r"(b[0]), "r"(b[1]));
}
__device__ __forceinline__ u32 smaddr(const void* p) {
    return (u32)__cvta_generic_to_shared(p);
}
// transposed ldmatrix: x4 (A m16k16 from [k][m] smem), x2 (B n8k16 from [k][n])
__device__ __forceinline__ void ldmT4(u32 a[4], u32 addr) {
    asm volatile("ldmatrix.sync.aligned.m8n8.x4.trans.shared.b16 {%0,%1,%2,%3},[%4];"
        : "=r"(a[0]), "=r"(a[1]), "=r"(a[2]), "=r"(a[3]) : "r"(addr) : "memory");
}
__device__ __forceinline__ void ldmT2(u32 b[2], u32 addr) {
    asm volatile("ldmatrix.sync.aligned.m8n8.x2.trans.shared.b16 {%0,%1},[%2];"
        : "=r"(b[0]), "=r"(b[1]) : "r"(addr) : "memory");
}
// scalar fragment loads from k-contiguous [row][stride] layouts
__device__ __forceinline__ void ldA(u32 a[4], const __nv_bfloat16* base, int stride,
                                    int mbase, int kbase, int lane) {
    const __nv_bfloat16* p = base + (size_t)(mbase + (lane >> 2)) * stride + kbase + (lane & 3) * 2;
    a[0] = *(const u32*)p;
    a[1] = *(const u32*)(p + 8 * stride);
    a[2] = *(const u32*)(p + 8);
    a[3] = *(const u32*)(p + 8 * stride + 8);
}
__device__ __forceinline__ void ldB(u32 b[2], const __nv_bfloat16* base, int stride,
                                    int nbase, int kbase, int lane) {
    const __nv_bfloat16* p = base + (size_t)(nbase + (lane >> 2)) * stride + kbase + (lane & 3) * 2;
    b[0] = *(const u32*)p;
    b[1] = *(const u32*)(p + 8);
}

// Scratch (device globals)
__device__ __nv_bfloat16 gQ[(size_t)Bk * HEADSk * Pk * HDk];   // [b][h][p][d], pre-scaled
__device__ __nv_bfloat16 gK[(size_t)Bk * HEADSk * Pk * HDk];   // [b][h][p][d]
__device__ __nv_bfloat16 gVt[(size_t)Bk * HEADSk * HDk * Pk];  // [b][h][d][p]
__device__ __nv_bfloat16 gO[(size_t)Bk * Pk * INTERk];         // [b][p][ci]

#define WS_STRIDE 40    // [co][k32] rows, conflict-free scalar frag loads
#define XS2       136   // [k32][px128] rows: 272B => 4-bank shift, conflict-free ldmatrix

// ---------------------------------------------------------------------------
// Kernel 1: QKV projection, bf16 HMMA, double-buffered + reg prefetch.
// grid = (P/128, B, 3), block = 256.
// z<2 (Q,K): C[px][co]  A = X (ldmatrix.trans from [k][px]), B = W
// z==2 (V):  C[co][px]  A = W, B = X (ldmatrix.trans)
// ---------------------------------------------------------------------------
__global__ __launch_bounds__(256, 2) void proj_kernel(
    const float* __restrict__ rgb, const float* __restrict__ depth, const float* __restrict__ rgbd,
    const float* __restrict__ Wq, const float* __restrict__ bq,
    const float* __restrict__ Wk, const float* __restrict__ bk,
    const float* __restrict__ Wv, const float* __restrict__ bv)
{
    __shared__ __nv_bfloat16 Ws[2][128 * WS_STRIDE];
    __shared__ __nv_bfloat16 Xs[2][32 * XS2];

    const int z = blockIdx.z;
    const float* x    = (z == 0) ? rgb : (z == 1) ? depth : rgbd;
    const float* W    = (z == 0) ? Wq  : (z == 1) ? Wk    : Wv;
    const float* bias = (z == 0) ? bq  : (z == 1) ? bk    : bv;

    const int b    = blockIdx.y;
    const int px0  = blockIdx.x * 128;
    const int t    = threadIdx.x;
    const int lane = t & 31;
    const int w    = t >> 5;
    const int wm   = w >> 1;
    const int wn   = w & 1;

    float c[16][4];
    #pragma unroll
    for (int i = 0; i < 16; i++)
        #pragma unroll
        for (int j = 0; j < 4; j++) c[i][j] = 0.f;

    const float* xb = x + (size_t)b * Ck * Pk + px0;

    // prefetch registers
    float4 pw0, pw1, pw2, pw3;       // W chunk slice
    float4 pxa0, pxa1, pxb0, pxb1;   // X chunk slices (k, k+16)

    const int wco = t >> 1, wkh = (t & 1) * 16;
    const int xk  = t >> 4, xp8 = (t & 15) * 8;

    auto ldg_chunk = [&](int kc) {
        const int ci0 = kc * 32;
        const float* wr = W + (size_t)wco * Ck + ci0 + wkh;
        pw0 = *(const float4*)(wr + 0);
        pw1 = *(const float4*)(wr + 4);
        pw2 = *(const float4*)(wr + 8);
        pw3 = *(const float4*)(wr + 12);
        const float* xr = xb + (size_t)(ci0 + xk) * Pk + xp8;
        pxa0 = *(const float4*)(xr);
        pxa1 = *(const float4*)(xr + 4);
        const float* xr2 = xb + (size_t)(ci0 + xk + 16) * Pk + xp8;
        pxb0 = *(const float4*)(xr2);
        pxb1 = *(const float4*)(xr2 + 4);
    };
    auto sts_chunk = [&](int buf) {
        uint4 p0, p1;
        p0.x = bf2(pw0.x, pw0.y); p0.y = bf2(pw0.z, pw0.w);
        p0.z = bf2(pw1.x, pw1.y); p0.w = bf2(pw1.z, pw1.w);
        p1.x = bf2(pw2.x, pw2.y); p1.y = bf2(pw2.z, pw2.w);
        p1.z = bf2(pw3.x, pw3.y); p1.w = bf2(pw3.z, pw3.w);
        *(uint4*)&Ws[buf][wco * WS_STRIDE + wkh]     = p0;
        *(uint4*)&Ws[buf][wco * WS_STRIDE + wkh + 8] = p1;
        uint4 xa, xbv;
        xa.x = bf2(pxa0.x, pxa0.y);  xa.y = bf2(pxa0.z, pxa0.w);
        xa.z = bf2(pxa1.x, pxa1.y);  xa.w = bf2(pxa1.z, pxa1.w);
        xbv.x = bf2(pxb0.x, pxb0.y); xbv.y = bf2(pxb0.z, pxb0.w);
        xbv.z = bf2(pxb1.x, pxb1.y); xbv.w = bf2(pxb1.z, pxb1.w);
        *(uint4*)&Xs[buf][xk * XS2 + xp8]        = xa;
        *(uint4*)&Xs[buf][(xk + 16) * XS2 + xp8] = xbv;
    };

    ldg_chunk(0);
    sts_chunk(0);

    #pragma unroll 2
    for (int kc = 0; kc < 8; kc++) {
        __syncthreads();
        if (kc < 7) ldg_chunk(kc + 1);

        const int buf = kc & 1;
        const __nv_bfloat16* XsB = &Xs[buf][0];
        const __nv_bfloat16* WsB = &Ws[buf][0];

        if (z < 2) {
            #pragma unroll
            for (int k16 = 0; k16 < 2; k16++) {
                u32 a0[4], a1[4];
                const int row  = k16 * 16 + ((lane & 16) >> 1) + (lane & 7);
                const int col0 = wm * 32 + (lane & 8);
                ldmT4(a0, smaddr(XsB + row * XS2 + col0));
                ldmT4(a1, smaddr(XsB + row * XS2 + col0 + 16));
                #pragma unroll
                for (int nt = 0; nt < 8; nt++) {
                    u32 bb[2];
                    ldB(bb, WsB, WS_STRIDE, wn * 64 + nt * 8, k16 * 16, lane);
                    mma16816(c[nt],     a0, bb);
                    mma16816(c[8 + nt], a1, bb);
                }
            }
        } else {
            #pragma unroll
            for (int k16 = 0; k16 < 2; k16++) {
                u32 a0[4], a1[4];
                ldA(a0, WsB, WS_STRIDE, wm * 32,      k16 * 16, lane);
                ldA(a1, WsB, WS_STRIDE, wm * 32 + 16, k16 * 16, lane);
                const int rowB = k16 * 16 + (lane & 15);
                #pragma unroll
                for (int nt = 0; nt < 8; nt++) {
                    u32 bb[2];
                    ldmT2(bb, smaddr(XsB + rowB * XS2 + wn * 64 + nt * 8));
                    mma16816(c[nt],     a0, bb);
                    mma16816(c[8 + nt], a1, bb);
                }
            }
        }
        if (kc < 7) sts_chunk((kc + 1) & 1);
    }

    // epilogue
    if (z < 2) {
        const float sc = (z == 0) ? 0.360673760f : 1.0f;   // Q: 0.25*log2(e)
        __nv_bfloat16* dst = (z == 0) ? gQ : gK;
        #pragma unroll
        for (int mt = 0; mt < 2; mt++)
            #pragma unroll
            for (int nt = 0; nt < 8; nt++) {
                const float* cc = c[mt * 8 + nt];
                const int px = px0 + wm * 32 + mt * 16 + (lane >> 2);
                const int co = wn * 64 + nt * 8 + (lane & 3) * 2;
                const int head = co >> 4, d = co & 15;
                const size_t base = (size_t)(b * HEADSk + head) * Pk;
                const float b0 = bias[co], b1 = bias[co + 1];
                *(u32*)&dst[(base + px) * HDk + d]     = bf2((cc[0] + b0) * sc, (cc[1] + b1) * sc);
                *(u32*)&dst[(base + px + 8) * HDk + d] = bf2((cc[2] + b0) * sc, (cc[3] + b1) * sc);
            }
    } else {
        #pragma unroll
        for (int mt = 0; mt < 2; mt++)
            #pragma unroll
            for (int nt = 0; nt < 8; nt++) {
                const float* cc = c[mt * 8 + nt];
                const int px = px0 + wn * 64 + nt * 8 + (lane & 3) * 2;
                #pragma unroll
                for (int half = 0; half < 2; half++) {
                    const int co = wm * 32 + mt * 16 + (lane >> 2) + half * 8;
                    const int head = co >> 4, d = co & 15;
                    const float bb = bias[co];
                    *(u32*)&gVt[((size_t)(b * HEADSk + head) * HDk + d) * Pk + px] =
                        bf2(cc[half * 2] + bb, cc[half * 2 + 1] + bb);
                }
            }
    }
}

// ---------------------------------------------------------------------------
// Kernel 2: attention, bf16 HMMA, double-buffered K/V + reg prefetch.
// grid = (P/128, HEADS, B), block = 256; warp owns 16 q rows.
// ---------------------------------------------------------------------------
__global__ __launch_bounds__(256, 2) void attn_kernel()
{
    __shared__ __nv_bfloat16 Ks[2][128][24];
    __shared__ __nv_bfloat16 Vs[2][16][136];

    const int tid  = threadIdx.x;
    const int lane = tid & 31;
    const int w    = tid >> 5;
    const int b = blockIdx.z, h = blockIdx.y;
    const size_t bh = (size_t)(b * HEADSk + h);
    const int qw = blockIdx.x * 128 + w * 16;

    const __nv_bfloat16* Qb = gQ  + bh * Pk * HDk;
    const __nv_bfloat16* Kb = gK  + bh * Pk * HDk;
    const __nv_bfloat16* Vb = gVt + bh * HDk * Pk;

    u32 aQ[4];
    {
        const __nv_bfloat16* qp = Qb + (size_t)(qw + (lane >> 2)) * HDk + (lane & 3) * 2;
        aQ[0] = *(const u32*)(qp);
        aQ[1] = *(const u32*)(qp + 8 * HDk);
        aQ[2] = *(const u32*)(qp + 8);
        aQ[3] = *(const u32*)(qp + 8 * HDk + 8);
    }

    float O0[4] = {0.f, 0.f, 0.f, 0.f};
    float O1[4] = {0.f, 0.f, 0.f, 0.f};
    float l0 = 0.f, l1 = 0.f;

    uint4 pk0, pk1, pv;
    const int vd = tid >> 4, vseg = (tid & 15) * 8;

    auto ldg_tile = [&](int kt) {
        if (tid < 128) {
            const uint4* src = (const uint4*)(Kb + (size_t)(kt + tid) * HDk);
            pk0 = src[0];
            pk1 = src[1];
        }
        pv = *(const uint4*)(Vb + (size_t)vd * Pk + kt + vseg);
    };
    auto sts_tile = [&](int buf) {
        if (tid < 128) {
            *(uint4*)&Ks[buf][tid][0] = pk0;
            *(uint4*)&Ks[buf][tid][8] = pk1;
        }
        *(uint4*)&Vs[buf][vd][vseg] = pv;
    };

    ldg_tile(0);
    sts_tile(0);

    #pragma unroll 2
    for (int it = 0; it < Pk / 128; it++) {
        __syncthreads();
        if (it < Pk / 128 - 1) ldg_tile((it + 1) * 128);
        const int buf = it & 1;

        float S[16][4];
        #pragma unroll
        for (int nt = 0; nt < 16; nt++) {
            S[nt][0] = 0.f; S[nt][1] = 0.f; S[nt][2] = 0.f; S[nt][3] = 0.f;
            u32 bK[2];
            bK[0] = *(const u32*)&Ks[buf][nt * 8 + (lane >> 2)][(lane & 3) * 2];
            bK[1] = *(const u32*)&Ks[buf][nt * 8 + (lane >> 2)][(lane & 3) * 2 + 8];
            mma16816(S[nt], aQ, bK);
        }

        #pragma unroll
        for (int nt = 0; nt < 16; nt++) {
            S[nt][0] = ex2f(S[nt][0]);
            S[nt][1] = ex2f(S[nt][1]);
            S[nt][2] = ex2f(S[nt][2]);
            S[nt][3] = ex2f(S[nt][3]);
            l0 += S[nt][0] + S[nt][1];
            l1 += S[nt][2] + S[nt][3];
        }

        #pragma unroll
        for (int kk = 0; kk < 8; kk++) {
            u32 aP[4];
            aP[0] = bf2(S[2*kk][0],   S[2*kk][1]);
            aP[1] = bf2(S[2*kk][2],   S[2*kk][3]);
            aP[2] = bf2(S[2*kk+1][0], S[2*kk+1][1]);
            aP[3] = bf2(S[2*kk+1][2], S[2*kk+1][3]);
            u32 bV[2];
            bV[0] = *(const u32*)&Vs[buf][(lane >> 2)][kk * 16 + (lane & 3) * 2];
            bV[1] = *(const u32*)&Vs[buf][(lane >> 2)][kk * 16 + (lane & 3) * 2 + 8];
            mma16816(O0, aP, bV);
            bV[0] = *(const u32*)&Vs[buf][8 + (lane >> 2)][kk * 16 + (lane & 3) * 2];
            bV[1] = *(const u32*)&Vs[buf][8 + (lane >> 2)][kk * 16 + (lane & 3) * 2 + 8];
            mma16816(O1, aP, bV);
        }
        if (it < Pk / 128 - 1) sts_tile((it + 1) & 1);
    }

    l0 += __shfl_xor_sync(0xffffffffu, l0, 1);
    l0 += __shfl_xor_sync(0xffffffffu, l0, 2);
    l1 += __shfl_xor_sync(0xffffffffu, l1, 1);
    l1 += __shfl_xor_sync(0xffffffffu, l1, 2);
    const float i0 = 1.f / l0;
    const float i1 = 1.f / l1;

    const int q = qw + (lane >> 2);
    __nv_bfloat16* Ob = gO + ((size_t)b * Pk) * INTERk + h * HDk;
    #pragma unroll
    for (int nd = 0; nd < 2; nd++) {
        const float* o = nd ? O1 : O0;
        const int d = nd * 8 + (lane & 3) * 2;
        *(u32*)&Ob[(size_t)q * INTERk + d]       = bf2(o[0] * i0, o[1] * i0);
        *(u32*)&Ob[(size_t)(q + 8) * INTERk + d] = bf2(o[2] * i1, o[3] * i1);
    }
}

// ---------------------------------------------------------------------------
// Kernel 3: output projection, single-stage (whole K=128 staged once).
// grid = (P/64, 2, B), block = 256. C[co][px]: A = Wo, B = O.
// Dynamic smem: Wos[128][136] + Os[64][136] bf16 = 52224 B.
// ---------------------------------------------------------------------------
#define OUT_SMEM ((128 + 64) * 136 * 2)

__global__ __launch_bounds__(256) void out_kernel(
    const float* __restrict__ rgb, const float* __restrict__ depth, const float* __restrict__ rgbd,
    const float* __restrict__ Wo, const float* __restrict__ bo,
    float* __restrict__ out)
{
    extern __shared__ __nv_bfloat16 dsm[];
    __nv_bfloat16* Wos = dsm;              // [128][136]
    __nv_bfloat16* Os  = dsm + 128 * 136;  // [64][136]

    const int b    = blockIdx.z;
    const int cob  = blockIdx.y;
    const int px0  = blockIdx.x * 64;
    const int t    = threadIdx.x;
    const int lane = t & 31;
    const int w    = t >> 5;
    const int wm   = w >> 1;   // co 32-blocks (4)
    const int wn   = w & 1;    // px 32-blocks (2)

    // stage Wo (fp32 -> bf16): thread covers 64 ci of one co row
    {
        const int co = t >> 1, ci0 = (t & 1) * 64;
        const float* wr = Wo + (size_t)(cob * 128 + co) * INTERk + ci0;
        #pragma unroll
        for (int i = 0; i < 4; i++) {
            const float4 f0 = *(const float4*)(wr + i * 16);
            const float4 f1 = *(const float4*)(wr + i * 16 + 4);
            const float4 f2 = *(const float4*)(wr + i * 16 + 8);
            const float4 f3 = *(const float4*)(wr + i * 16 + 12);
            uint4 p, q;
            p.x = bf2(f0.x, f0.y); p.y = bf2(f0.z, f0.w);
            p.z = bf2(f1.x, f1.y); p.w = bf2(f1.z, f1.w);
            q.x = bf2(f2.x, f2.y); q.y = bf2(f2.z, f2.w);
            q.z = bf2(f3.x, f3.y); q.w = bf2(f3.z, f3.w);
            *(uint4*)&Wos[co * 136 + ci0 + i * 16]     = p;
            *(uint4*)&Wos[co * 136 + ci0 + i * 16 + 8] = q;
        }
    }
    // stage O (already bf16 [px][ci])
    {
        const int px = t >> 2, ci0 = (t & 3) * 32;
        const __nv_bfloat16* src = gO + ((size_t)b * Pk + px0 + px) * INTERk + ci0;
        *(uint4*)&Os[px * 136 + ci0]      = *(const uint4*)(src);
        *(uint4*)&Os[px * 136 + ci0 + 8]  = *(const uint4*)(src + 8);
        *(uint4*)&Os[px * 136 + ci0 + 16] = *(const uint4*)(src + 16);
        *(uint4*)&Os[px * 136 + ci0 + 24] = *(const uint4*)(src + 24);
    }
    __syncthreads();

    float c[8][4];
    #pragma unroll
    for (int i = 0; i < 8; i++)
        #pragma unroll
        for (int j = 0; j < 4; j++) c[i][j] = 0.f;

    #pragma unroll
    for (int k16 = 0; k16 < 8; k16++) {
        u32 a0[4], a1[4];
        ldA(a0, Wos, 136, wm * 32,      k16 * 16, lane);
        ldA(a1, Wos, 136, wm * 32 + 16, k16 * 16, lane);
        #pragma unroll
        for (int nt = 0; nt < 4; nt++) {
            u32 bb[2];
            ldB(bb, Os, 136, wn * 32 + nt * 8, k16 * 16, lane);
            mma16816(c[nt],     a0, bb);
            mma16816(c[4 + nt], a1, bb);
        }
    }

    const size_t N1 = (size_t)Bk * Ck * Pk;
    #pragma unroll
    for (int mt = 0; mt < 2; mt++)
        #pragma unroll
        for (int nt = 0; nt < 4; nt++) {
            const float* cc = c[mt * 4 + nt];
            const int px = px0 + wn * 32 + nt * 8 + (lane & 3) * 2;
            #pragma unroll
            for (int half = 0; half < 2; half++) {
                const int co = cob * 128 + wm * 32 + mt * 16 + (lane >> 2) + half * 8;
                const float bb = bo[co];
                const float r0 = cc[half * 2]     + bb;
                const float r1 = cc[half * 2 + 1] + bb;
                const size_t idx = ((size_t)b * Ck + co) * Pk + px;
                const float2 a0 = *(const float2*)(rgb   + idx);
                const float2 a1 = *(const float2*)(depth + idx);
                const float2 a2 = *(const float2*)(rgbd  + idx);
                *(float2*)(out + idx)          = make_float2(a0.x + r0, a0.y + r1);
                *(float2*)(out + N1 + idx)     = make_float2(a1.x + r0, a1.y + r1);
                *(float2*)(out + 2 * N1 + idx) = make_float2(a2.x + r0, a2.y + r1);
            }
        }
}

// ---------------------------------------------------------------------------
extern "C" void kernel_launch(void* const* d_in, const int* in_sizes, int n_in,
                              void* d_out, int out_size)
{
    const float* rgb   = (const float*)d_in[0];
    const float* depth = (const float*)d_in[1];
    const float* rgbd  = (const float*)d_in[2];
    const float* Wq = (const float*)d_in[3];
    const float* bq = (const float*)d_in[4];
    const float* Wk = (const float*)d_in[5];
    const float* bk = (const float*)d_in[6];
    const float* Wv = (const float*)d_in[7];
    const float* bv = (const float*)d_in[8];
    const float* Wo = (const float*)d_in[9];
    const float* bo = (const float*)d_in[10];
    float* out = (float*)d_out;

    static bool attr_set = false;
    if (!attr_set) {
        cudaFuncSetAttribute(out_kernel, cudaFuncAttributeMaxDynamicSharedMemorySize, OUT_SMEM);
        attr_set = true;
    }

    proj_kernel<<<dim3(Pk / 128, Bk, 3), 256>>>(rgb, depth, rgbd,
                                                Wq, bq, Wk, bk, Wv, bv);
    attn_kernel<<<dim3(Pk / 128, HEADSk, Bk), 256>>>();
    out_kernel<<<dim3(Pk / 64, 2, Bk), 256, OUT_SMEM>>>(rgb, depth, rgbd, Wo, bo, out);
}

// round 10
// speedup vs baseline: 8.0937x; 1.0285x over previous
#include <cuda_runtime.h>
#include <cuda_fp16.h>

#define Bk      4
#define Ck      256
#define Pk      2304      // 48*48
#define INTERk  128
#define HEADSk  8
#define HDk     16

typedef unsigned long long u64;
typedef unsigned int u32;

// ---- helpers --------------------------------------------------------------
// pack two f32 -> f16x2 (lo, hi)
__device__ __forceinline__ u32 h2(float lo, float hi) {
    u32 r; asm("cvt.rn.f16x2.f32 %0,%1,%2;" : "=r"(r) : "f"(hi), "f"(lo)); return r;
}
__device__ __forceinline__ u32 ex2h2(u32 x) {
    u32 r; asm("ex2.approx.f16x2 %0,%1;" : "=r"(r) : "r"(x)); return r;
}
__device__ __forceinline__ u32 hadd2(u32 a, u32 b) {
    u32 r; asm("add.rn.f16x2 %0,%1,%2;" : "=r"(r) : "r"(a), "r"(b)); return r;
}
__device__ __forceinline__ float2 h2f(u32 h) {
    float2 f;
    asm("{.reg .f16 l,h; mov.b32 {l,h},%2; cvt.f32.f16 %0,l; cvt.f32.f16 %1,h;}"
        : "=f"(f.x), "=f"(f.y) : "r"(h));
    return f;
}
// mma m16n8k16 fp16 -> f32 accum
__device__ __forceinline__ void mma16816(float c[4], const u32 a[4], const u32 b[2]) {
    asm("mma.sync.aligned.m16n8k16.row.col.f32.f16.f16.f32 "
        "{%0,%1,%2,%3},{%4,%5,%6,%7},{%8,%9},{%0,%1,%2,%3};"
        : "+f"(c[0]), "+f"(c[1]), "+f"(c[2]), "+f"(c[3])
        : "r"(a[0]), "r"(a[1]), "r"(a[2]), "r"(a[3]), "r"(b[0]), "r"(b[1]));
}
__device__ __forceinline__ u32 smaddr(const void* p) {
    return (u32)__cvta_generic_to_shared(p);
}
__device__ __forceinline__ void ldmT4(u32 a[4], u32 addr) {
    asm volatile("ldmatrix.sync.aligned.m8n8.x4.trans.shared.b16 {%0,%1,%2,%3},[%4];"
        : "=r"(a[0]), "=r"(a[1]), "=r"(a[2]), "=r"(a[3]) : "r"(addr) : "memory");
}
__device__ __forceinline__ void ldmT2(u32 b[2], u32 addr) {
    asm volatile("ldmatrix.sync.aligned.m8n8.x2.trans.shared.b16 {%0,%1},[%2];"
        : "=r"(b[0]), "=r"(b[1]) : "r"(addr) : "memory");
}
__device__ __forceinline__ void ldA(u32 a[4], const __half* base, int stride,
                                    int mbase, int kbase, int lane) {
    const __half* p = base + (size_t)(mbase + (lane >> 2)) * stride + kbase + (lane & 3) * 2;
    a[0] = *(const u32*)p;
    a[1] = *(const u32*)(p + 8 * stride);
    a[2] = *(const u32*)(p + 8);
    a[3] = *(const u32*)(p + 8 * stride + 8);
}
__device__ __forceinline__ void ldB(u32 b[2], const __half* base, int stride,
                                    int nbase, int kbase, int lane) {
    const __half* p = base + (size_t)(nbase + (lane >> 2)) * stride + kbase + (lane & 3) * 2;
    b[0] = *(const u32*)p;
    b[1] = *(const u32*)(p + 8);
}

// Scratch (device globals), all fp16
__device__ __half gQ[(size_t)Bk * HEADSk * Pk * HDk];   // [b][h][p][d], pre-scaled
__device__ __half gK[(size_t)Bk * HEADSk * Pk * HDk];   // [b][h][p][d]
__device__ __half gVt[(size_t)Bk * HEADSk * HDk * Pk];  // [b][h][d][p]
__device__ __half gO[(size_t)Bk * Pk * INTERk];         // [b][p][ci]

#define WS_STRIDE 40
#define XS2       136

// ---------------------------------------------------------------------------
// Kernel 1: QKV projection, fp16 HMMA, double-buffered + reg prefetch.
// ---------------------------------------------------------------------------
__global__ __launch_bounds__(256, 2) void proj_kernel(
    const float* __restrict__ rgb, const float* __restrict__ depth, const float* __restrict__ rgbd,
    const float* __restrict__ Wq, const float* __restrict__ bq,
    const float* __restrict__ Wk, const float* __restrict__ bk,
    const float* __restrict__ Wv, const float* __restrict__ bv)
{
    __shared__ __half Ws[2][128 * WS_STRIDE];
    __shared__ __half Xs[2][32 * XS2];

    const int z = blockIdx.z;
    const float* x    = (z == 0) ? rgb : (z == 1) ? depth : rgbd;
    const float* W    = (z == 0) ? Wq  : (z == 1) ? Wk    : Wv;
    const float* bias = (z == 0) ? bq  : (z == 1) ? bk    : bv;

    const int b    = blockIdx.y;
    const int px0  = blockIdx.x * 128;
    const int t    = threadIdx.x;
    const int lane = t & 31;
    const int w    = t >> 5;
    const int wm   = w >> 1;
    const int wn   = w & 1;

    float c[16][4];
    #pragma unroll
    for (int i = 0; i < 16; i++)
        #pragma unroll
        for (int j = 0; j < 4; j++) c[i][j] = 0.f;

    const float* xb = x + (size_t)b * Ck * Pk + px0;

    float4 pw0, pw1, pw2, pw3;
    float4 pxa0, pxa1, pxb0, pxb1;

    const int wco = t >> 1, wkh = (t & 1) * 16;
    const int xk  = t >> 4, xp8 = (t & 15) * 8;

    auto ldg_chunk = [&](int kc) {
        const int ci0 = kc * 32;
        const float* wr = W + (size_t)wco * Ck + ci0 + wkh;
        pw0 = *(const float4*)(wr + 0);
        pw1 = *(const float4*)(wr + 4);
        pw2 = *(const float4*)(wr + 8);
        pw3 = *(const float4*)(wr + 12);
        const float* xr = xb + (size_t)(ci0 + xk) * Pk + xp8;
        pxa0 = *(const float4*)(xr);
        pxa1 = *(const float4*)(xr + 4);
        const float* xr2 = xb + (size_t)(ci0 + xk + 16) * Pk + xp8;
        pxb0 = *(const float4*)(xr2);
        pxb1 = *(const float4*)(xr2 + 4);
    };
    auto sts_chunk = [&](int buf) {
        uint4 p0, p1;
        p0.x = h2(pw0.x, pw0.y); p0.y = h2(pw0.z, pw0.w);
        p0.z = h2(pw1.x, pw1.y); p0.w = h2(pw1.z, pw1.w);
        p1.x = h2(pw2.x, pw2.y); p1.y = h2(pw2.z, pw2.w);
        p1.z = h2(pw3.x, pw3.y); p1.w = h2(pw3.z, pw3.w);
        *(uint4*)&Ws[buf][wco * WS_STRIDE + wkh]     = p0;
        *(uint4*)&Ws[buf][wco * WS_STRIDE + wkh + 8] = p1;
        uint4 xa, xbv;
        xa.x = h2(pxa0.x, pxa0.y);  xa.y = h2(pxa0.z, pxa0.w);
        xa.z = h2(pxa1.x, pxa1.y);  xa.w = h2(pxa1.z, pxa1.w);
        xbv.x = h2(pxb0.x, pxb0.y); xbv.y = h2(pxb0.z, pxb0.w);
        xbv.z = h2(pxb1.x, pxb1.y); xbv.w = h2(pxb1.z, pxb1.w);
        *(uint4*)&Xs[buf][xk * XS2 + xp8]        = xa;
        *(uint4*)&Xs[buf][(xk + 16) * XS2 + xp8] = xbv;
    };

    ldg_chunk(0);
    sts_chunk(0);

    #pragma unroll 2
    for (int kc = 0; kc < 8; kc++) {
        __syncthreads();
        if (kc < 7) ldg_chunk(kc + 1);

        const int buf = kc & 1;
        const __half* XsB = &Xs[buf][0];
        const __half* WsB = &Ws[buf][0];

        if (z < 2) {
            #pragma unroll
            for (int k16 = 0; k16 < 2; k16++) {
                u32 a0[4], a1[4];
                const int row  = k16 * 16 + ((lane & 16) >> 1) + (lane & 7);
                const int col0 = wm * 32 + (lane & 8);
                ldmT4(a0, smaddr(XsB + row * XS2 + col0));
                ldmT4(a1, smaddr(XsB + row * XS2 + col0 + 16));
                #pragma unroll
                for (int nt = 0; nt < 8; nt++) {
                    u32 bb[2];
                    ldB(bb, WsB, WS_STRIDE, wn * 64 + nt * 8, k16 * 16, lane);
                    mma16816(c[nt],     a0, bb);
                    mma16816(c[8 + nt], a1, bb);
                }
            }
        } else {
            #pragma unroll
            for (int k16 = 0; k16 < 2; k16++) {
                u32 a0[4], a1[4];
                ldA(a0, WsB, WS_STRIDE, wm * 32,      k16 * 16, lane);
                ldA(a1, WsB, WS_STRIDE, wm * 32 + 16, k16 * 16, lane);
                const int rowB = k16 * 16 + (lane & 15);
                #pragma unroll
                for (int nt = 0; nt < 8; nt++) {
                    u32 bb[2];
                    ldmT2(bb, smaddr(XsB + rowB * XS2 + wn * 64 + nt * 8));
                    mma16816(c[nt],     a0, bb);
                    mma16816(c[8 + nt], a1, bb);
                }
            }
        }
        if (kc < 7) sts_chunk((kc + 1) & 1);
    }

    // epilogue
    if (z < 2) {
        const float sc = (z == 0) ? 0.360673760f : 1.0f;   // Q: 0.25*log2(e)
        __half* dst = (z == 0) ? gQ : gK;
        #pragma unroll
        for (int mt = 0; mt < 2; mt++)
            #pragma unroll
            for (int nt = 0; nt < 8; nt++) {
                const float* cc = c[mt * 8 + nt];
                const int px = px0 + wm * 32 + mt * 16 + (lane >> 2);
                const int co = wn * 64 + nt * 8 + (lane & 3) * 2;
                const int head = co >> 4, d = co & 15;
                const size_t base = (size_t)(b * HEADSk + head) * Pk;
                const float b0 = bias[co], b1 = bias[co + 1];
                *(u32*)&dst[(base + px) * HDk + d]     = h2((cc[0] + b0) * sc, (cc[1] + b1) * sc);
                *(u32*)&dst[(base + px + 8) * HDk + d] = h2((cc[2] + b0) * sc, (cc[3] + b1) * sc);
            }
    } else {
        #pragma unroll
        for (int mt = 0; mt < 2; mt++)
            #pragma unroll
            for (int nt = 0; nt < 8; nt++) {
                const float* cc = c[mt * 8 + nt];
                const int px = px0 + wn * 64 + nt * 8 + (lane & 3) * 2;
                #pragma unroll
                for (int half = 0; half < 2; half++) {
                    const int co = wm * 32 + mt * 16 + (lane >> 2) + half * 8;
                    const int head = co >> 4, d = co & 15;
                    const float bb = bias[co];
                    *(u32*)&gVt[((size_t)(b * HEADSk + head) * HDk + d) * Pk + px] =
                        h2(cc[half * 2] + bb, cc[half * 2 + 1] + bb);
                }
            }
    }
}

// ---------------------------------------------------------------------------
// Kernel 2: attention, fp16 HMMA, packed f16x2 exp, double-buffered K/V.
// grid = (P/128, HEADS, B), block = 256; warp owns 16 q rows.
// ---------------------------------------------------------------------------
__global__ __launch_bounds__(256, 2) void attn_kernel()
{
    __shared__ __half Ks[2][128][24];
    __shared__ __half Vs[2][16][136];

    const int tid  = threadIdx.x;
    const int lane = tid & 31;
    const int w    = tid >> 5;
    const int b = blockIdx.z, h = blockIdx.y;
    const size_t bh = (size_t)(b * HEADSk + h);
    const int qw = blockIdx.x * 128 + w * 16;

    const __half* Qb = gQ  + bh * Pk * HDk;
    const __half* Kb = gK  + bh * Pk * HDk;
    const __half* Vb = gVt + bh * HDk * Pk;

    u32 aQ[4];
    {
        const __half* qp = Qb + (size_t)(qw + (lane >> 2)) * HDk + (lane & 3) * 2;
        aQ[0] = *(const u32*)(qp);
        aQ[1] = *(const u32*)(qp + 8 * HDk);
        aQ[2] = *(const u32*)(qp + 8);
        aQ[3] = *(const u32*)(qp + 8 * HDk + 8);
    }

    float O0[4] = {0.f, 0.f, 0.f, 0.f};
    float O1[4] = {0.f, 0.f, 0.f, 0.f};
    float l0 = 0.f, l1 = 0.f;

    uint4 pk0, pk1, pv;
    const int vd = tid >> 4, vseg = (tid & 15) * 8;

    auto ldg_tile = [&](int kt) {
        if (tid < 128) {
            const uint4* src = (const uint4*)(Kb + (size_t)(kt + tid) * HDk);
            pk0 = src[0];
            pk1 = src[1];
        }
        pv = *(const uint4*)(Vb + (size_t)vd * Pk + kt + vseg);
    };
    auto sts_tile = [&](int buf) {
        if (tid < 128) {
            *(uint4*)&Ks[buf][tid][0] = pk0;
            *(uint4*)&Ks[buf][tid][8] = pk1;
        }
        *(uint4*)&Vs[buf][vd][vseg] = pv;
    };

    ldg_tile(0);
    sts_tile(0);

    #pragma unroll 2
    for (int it = 0; it < Pk / 128; it++) {
        __syncthreads();
        if (it < Pk / 128 - 1) ldg_tile((it + 1) * 128);
        const int buf = it & 1;

        float S[16][4];
        #pragma unroll
        for (int nt = 0; nt < 16; nt++) {
            S[nt][0] = 0.f; S[nt][1] = 0.f; S[nt][2] = 0.f; S[nt][3] = 0.f;
            u32 bK[2];
            bK[0] = *(const u32*)&Ks[buf][nt * 8 + (lane >> 2)][(lane & 3) * 2];
            bK[1] = *(const u32*)&Ks[buf][nt * 8 + (lane >> 2)][(lane & 3) * 2 + 8];
            mma16816(S[nt], aQ, bK);
        }

        // packed fp16 exp: e[nt][0] = exp2 of cols pair (row r), e[nt][1] (row r+8)
        u32 e[16][2];
        #pragma unroll
        for (int nt = 0; nt < 16; nt++) {
            e[nt][0] = ex2h2(h2(S[nt][0], S[nt][1]));
            e[nt][1] = ex2h2(h2(S[nt][2], S[nt][3]));
        }
        // tile row-sums in f16x2, flush to f32 once per tile
        u32 ta = e[0][0], tb = e[0][1];
        #pragma unroll
        for (int nt = 1; nt < 16; nt++) {
            ta = hadd2(ta, e[nt][0]);
            tb = hadd2(tb, e[nt][1]);
        }
        const float2 fa = h2f(ta), fb = h2f(tb);
        l0 += fa.x + fa.y;
        l1 += fb.x + fb.y;

        // O += P * V (P fragments are the ex2 outputs directly)
        #pragma unroll
        for (int kk = 0; kk < 8; kk++) {
            u32 aP[4];
            aP[0] = e[2*kk][0];
            aP[1] = e[2*kk][1];
            aP[2] = e[2*kk+1][0];
            aP[3] = e[2*kk+1][1];
            u32 bV[2];
            bV[0] = *(const u32*)&Vs[buf][(lane >> 2)][kk * 16 + (lane & 3) * 2];
            bV[1] = *(const u32*)&Vs[buf][(lane >> 2)][kk * 16 + (lane & 3) * 2 + 8];
            mma16816(O0, aP, bV);
            bV[0] = *(const u32*)&Vs[buf][8 + (lane >> 2)][kk * 16 + (lane & 3) * 2];
            bV[1] = *(const u32*)&Vs[buf][8 + (lane >> 2)][kk * 16 + (lane & 3) * 2 + 8];
            mma16816(O1, aP, bV);
        }
        if (it < Pk / 128 - 1) sts_tile((it + 1) & 1);
    }

    l0 += __shfl_xor_sync(0xffffffffu, l0, 1);
    l0 += __shfl_xor_sync(0xffffffffu, l0, 2);
    l1 += __shfl_xor_sync(0xffffffffu, l1, 1);
    l1 += __shfl_xor_sync(0xffffffffu, l1, 2);
    const float i0 = 1.f / l0;
    const float i1 = 1.f / l1;

    const int q = qw + (lane >> 2);
    __half* Ob = gO + ((size_t)b * Pk) * INTERk + h * HDk;
    #pragma unroll
    for (int nd = 0; nd < 2; nd++) {
        const float* o = nd ? O1 : O0;
        const int d = nd * 8 + (lane & 3) * 2;
        *(u32*)&Ob[(size_t)q * INTERk + d]       = h2(o[0] * i0, o[1] * i0);
        *(u32*)&Ob[(size_t)(q + 8) * INTERk + d] = h2(o[2] * i1, o[3] * i1);
    }
}

// ---------------------------------------------------------------------------
// Kernel 3: output projection, single-stage, fp16 HMMA + bias + 3x residual.
// ---------------------------------------------------------------------------
#define OUT_SMEM ((128 + 64) * 136 * 2)

__global__ __launch_bounds__(256) void out_kernel(
    const float* __restrict__ rgb, const float* __restrict__ depth, const float* __restrict__ rgbd,
    const float* __restrict__ Wo, const float* __restrict__ bo,
    float* __restrict__ out)
{
    extern __shared__ __half dsm[];
    __half* Wos = dsm;              // [128][136]
    __half* Os  = dsm + 128 * 136;  // [64][136]

    const int b    = blockIdx.z;
    const int cob  = blockIdx.y;
    const int px0  = blockIdx.x * 64;
    const int t    = threadIdx.x;
    const int lane = t & 31;
    const int w    = t >> 5;
    const int wm   = w >> 1;
    const int wn   = w & 1;

    {
        const int co = t >> 1, ci0 = (t & 1) * 64;
        const float* wr = Wo + (size_t)(cob * 128 + co) * INTERk + ci0;
        #pragma unroll
        for (int i = 0; i < 4; i++) {
            const float4 f0 = *(const float4*)(wr + i * 16);
            const float4 f1 = *(const float4*)(wr + i * 16 + 4);
            const float4 f2 = *(const float4*)(wr + i * 16 + 8);
            const float4 f3 = *(const float4*)(wr + i * 16 + 12);
            uint4 p, q;
            p.x = h2(f0.x, f0.y); p.y = h2(f0.z, f0.w);
            p.z = h2(f1.x, f1.y); p.w = h2(f1.z, f1.w);
            q.x = h2(f2.x, f2.y); q.y = h2(f2.z, f2.w);
            q.z = h2(f3.x, f3.y); q.w = h2(f3.z, f3.w);
            *(uint4*)&Wos[co * 136 + ci0 + i * 16]     = p;
            *(uint4*)&Wos[co * 136 + ci0 + i * 16 + 8] = q;
        }
    }
    {
        const int px = t >> 2, ci0 = (t & 3) * 32;
        const __half* src = gO + ((size_t)b * Pk + px0 + px) * INTERk + ci0;
        *(uint4*)&Os[px * 136 + ci0]      = *(const uint4*)(src);
        *(uint4*)&Os[px * 136 + ci0 + 8]  = *(const uint4*)(src + 8);
        *(uint4*)&Os[px * 136 + ci0 + 16] = *(const uint4*)(src + 16);
        *(uint4*)&Os[px * 136 + ci0 + 24] = *(const uint4*)(src + 24);
    }
    __syncthreads();

    float c[8][4];
    #pragma unroll
    for (int i = 0; i < 8; i++)
        #pragma unroll
        for (int j = 0; j < 4; j++) c[i][j] = 0.f;

    #pragma unroll
    for (int k16 = 0; k16 < 8; k16++) {
        u32 a0[4], a1[4];
        ldA(a0, Wos, 136, wm * 32,      k16 * 16, lane);
        ldA(a1, Wos, 136, wm * 32 + 16, k16 * 16, lane);
        #pragma unroll
        for (int nt = 0; nt < 4; nt++) {
            u32 bb[2];
            ldB(bb, Os, 136, wn * 32 + nt * 8, k16 * 16, lane);
            mma16816(c[nt],     a0, bb);
            mma16816(c[4 + nt], a1, bb);
        }
    }

    const size_t N1 = (size_t)Bk * Ck * Pk;
    #pragma unroll
    for (int mt = 0; mt < 2; mt++)
        #pragma unroll
        for (int nt = 0; nt < 4; nt++) {
            const float* cc = c[mt * 4 + nt];
            const int px = px0 + wn * 32 + nt * 8 + (lane & 3) * 2;
            #pragma unroll
            for (int half = 0; half < 2; half++) {
                const int co = cob * 128 + wm * 32 + mt * 16 + (lane >> 2) + half * 8;
                const float bb = bo[co];
                const float r0 = cc[half * 2]     + bb;
                const float r1 = cc[half * 2 + 1] + bb;
                const size_t idx = ((size_t)b * Ck + co) * Pk + px;
                const float2 a0 = *(const float2*)(rgb   + idx);
                const float2 a1 = *(const float2*)(depth + idx);
                const float2 a2 = *(const float2*)(rgbd  + idx);
                *(float2*)(out + idx)          = make_float2(a0.x + r0, a0.y + r1);
                *(float2*)(out + N1 + idx)     = make_float2(a1.x + r0, a1.y + r1);
                *(float2*)(out + 2 * N1 + idx) = make_float2(a2.x + r0, a2.y + r1);
            }
        }
}

// ---------------------------------------------------------------------------
extern "C" void kernel_launch(void* const* d_in, const int* in_sizes, int n_in,
                              void* d_out, int out_size)
{
    const float* rgb   = (const float*)d_in[0];
    const float* depth = (const float*)d_in[1];
    const float* rgbd  = (const float*)d_in[2];
    const float* Wq = (const float*)d_in[3];
    const float* bq = (const float*)d_in[4];
    const float* Wk = (const float*)d_in[5];
    const float* bk = (const float*)d_in[6];
    const float* Wv = (const float*)d_in[7];
    const float* bv = (const float*)d_in[8];
    const float* Wo = (const float*)d_in[9];
    const float* bo = (const float*)d_in[10];
    float* out = (float*)d_out;

    static bool attr_set = false;
    if (!attr_set) {
        cudaFuncSetAttribute(out_kernel, cudaFuncAttributeMaxDynamicSharedMemorySize, OUT_SMEM);
        attr_set = true;
    }

    proj_kernel<<<dim3(Pk / 128, Bk, 3), 256>>>(rgb, depth, rgbd,
                                                Wq, bq, Wk, bk, Wv, bv);
    attn_kernel<<<dim3(Pk / 128, HEADSk, Bk), 256>>>();
    out_kernel<<<dim3(Pk / 64, 2, Bk), 256, OUT_SMEM>>>(rgb, depth, rgbd, Wo, bo, out);
}